// round 12
// baseline (speedup 1.0000x reference)
#include <cuda_runtime.h>
#include <cuda_fp16.h>
#include <math.h>
#include <stdint.h>
#include <string.h>

#define D_MODEL 1024
#define NTOK    8192   // B*T
#define HEADS   16
#define HD      64
#define TSEQ    2048
#define BATCH   4

// fp16 GEMM tiling
#define BM 128
#define BN 128
#define BK32 32
#define PAW 20    // A smem pitch in 32-bit words (40 fp16)
#define PBW 132   // B smem pitch in words per k-pair row

// Attention fp16 smem pitch (fp16 elements). 72*2B=144B rows; 36 words.
#define PB   72
#define PB32 36

// Scratch (no allocation allowed — device globals). 16B-aligned.
__device__ __align__(16) float g_Q[NTOK * D_MODEL];
__device__ __align__(16) float g_K[NTOK * D_MODEL];
__device__ __align__(16) float g_V[NTOK * D_MODEL];
__device__ __align__(16) float g_A[NTOK * D_MODEL];
// Pre-packed fp16 weights, k-pair layout: word[(k/2)*1024 + n] = {W[k][n], W[k+1][n]}
__device__ __align__(16) uint32_t g_W16[4][(D_MODEL / 2) * D_MODEL];

__device__ __forceinline__ void mma_f16(float* c, const uint32_t* a, uint32_t b0, uint32_t b1) {
    asm volatile(
        "mma.sync.aligned.m16n8k16.row.col.f32.f16.f16.f32 "
        "{%0,%1,%2,%3}, {%4,%5,%6,%7}, {%8,%9}, {%0,%1,%2,%3};\n"
        : "+f"(c[0]), "+f"(c[1]), "+f"(c[2]), "+f"(c[3])
        : "r"(a[0]), "r"(a[1]), "r"(a[2]), "r"(a[3]), "r"(b0), "r"(b1));
}

// split fp32 -> fp16 hi + fp16 lo (hi+lo reproduces ~22 mantissa bits)
__device__ __forceinline__ void hsplit(float x, __half& h, __half& l) {
    h = __float2half_rn(x);
    l = __float2half_rn(x - __half2float(h));
}

// pack two fp16 into one 32-bit word (lo -> low half)
__device__ __forceinline__ uint32_t pack2h(__half lo, __half hi) {
    __half2 p = __halves2half2(lo, hi);
    uint32_t u;
    memcpy(&u, &p, 4);
    return u;
}

// single-instruction fp32x2 -> fp16x2 (lo in low half)
__device__ __forceinline__ uint32_t packf2(float lo, float hi) {
    __half2 p = __floats2half2_rn(lo, hi);
    uint32_t u;
    memcpy(&u, &p, 4);
    return u;
}

// ---------------------------------------------------------------------------
// Weight pre-pack: fp32 [1024][1024] -> fp16 k-pair words [512][1024].
// blockIdx.y selects the matrix.
// ---------------------------------------------------------------------------
__global__ __launch_bounds__(256)
void pack_w16_kernel(const float* __restrict__ Wq, const float* __restrict__ Wk,
                     const float* __restrict__ Wv, const float* __restrict__ Wo)
{
    const float* W = (blockIdx.y == 0) ? Wq : (blockIdx.y == 1) ? Wk
                   : (blockIdx.y == 2) ? Wv : Wo;
    uint32_t* out = g_W16[blockIdx.y];
    int idx = blockIdx.x * 256 + threadIdx.x;      // 0 .. 512*1024-1
    int k2 = idx >> 10, n = idx & 1023;
    float w0 = W[(size_t)(2 * k2) * D_MODEL + n];
    float w1 = W[(size_t)(2 * k2 + 1) * D_MODEL + n];
    out[idx] = packf2(w0, w1);
}

// ---------------------------------------------------------------------------
// fp16 tensor-core GEMM: C[M,N] = A[M,K] @ B[K,N] + bias[N].
// A fp32 (converted at STS), B pre-packed fp16 k-pairs. 128x128 tile, BK=32,
// 256 threads / 8 warps, warp tile 64x32. Single-buffer, register prefetch
// (the proven fine-interleave structure).
// ---------------------------------------------------------------------------
__global__ __launch_bounds__(256, 2)
void gemm_f16_bias(const float* __restrict__ A, const uint32_t* __restrict__ B16,
                   const float* __restrict__ bias, float* __restrict__ C)
{
    __shared__ uint32_t As[BM * PAW];     // [row][k-word], 40 fp16 per row
    __shared__ uint32_t Bs[16 * PBW];     // [k2][n] fp16-pair words

    const int tid  = threadIdx.x;
    const int warp = tid >> 5, lane = tid & 31;
    const int g = lane >> 2, t = lane & 3;
    const int wm = (warp >> 2) * 64;
    const int wn = (warp & 3) * 32;

    const int bx = blockIdx.x, by = blockIdx.y;
    const float* Ab = A + (size_t)by * BM * D_MODEL;
    const uint32_t* Bb = B16 + bx * BN;

    // global load assignment
    const int arow = tid >> 1, acolf = (tid & 1) * 16;    // A: 16 floats/thread
    const int brow = tid >> 4, bcolw = (tid & 15) * 8;    // B: 8 words/thread

    float4 pa0 = *(const float4*)(Ab + (size_t)arow * D_MODEL + acolf);
    float4 pa1 = *(const float4*)(Ab + (size_t)arow * D_MODEL + acolf + 4);
    float4 pa2 = *(const float4*)(Ab + (size_t)arow * D_MODEL + acolf + 8);
    float4 pa3 = *(const float4*)(Ab + (size_t)arow * D_MODEL + acolf + 12);
    uint4 pb0 = *(const uint4*)(Bb + (size_t)brow * D_MODEL + bcolw);
    uint4 pb1 = *(const uint4*)(Bb + (size_t)brow * D_MODEL + bcolw + 4);

    float acc[4][4][4];
#pragma unroll
    for (int mt = 0; mt < 4; mt++)
#pragma unroll
        for (int nt = 0; nt < 4; nt++)
#pragma unroll
            for (int i = 0; i < 4; i++) acc[mt][nt][i] = 0.f;

    for (int k0 = 0; k0 < D_MODEL; k0 += BK32) {
        // commit staged registers to smem
        {
            uint4 w0 = make_uint4(packf2(pa0.x, pa0.y), packf2(pa0.z, pa0.w),
                                  packf2(pa1.x, pa1.y), packf2(pa1.z, pa1.w));
            uint4 w1 = make_uint4(packf2(pa2.x, pa2.y), packf2(pa2.z, pa2.w),
                                  packf2(pa3.x, pa3.y), packf2(pa3.z, pa3.w));
            *(uint4*)&As[arow * PAW + (acolf >> 1)]     = w0;
            *(uint4*)&As[arow * PAW + (acolf >> 1) + 4] = w1;
            *(uint4*)&Bs[brow * PBW + bcolw]     = pb0;
            *(uint4*)&Bs[brow * PBW + bcolw + 4] = pb1;
        }
        __syncthreads();

        // prefetch next stage (hidden behind MMAs)
        if (k0 + BK32 < D_MODEL) {
            pa0 = *(const float4*)(Ab + (size_t)arow * D_MODEL + k0 + BK32 + acolf);
            pa1 = *(const float4*)(Ab + (size_t)arow * D_MODEL + k0 + BK32 + acolf + 4);
            pa2 = *(const float4*)(Ab + (size_t)arow * D_MODEL + k0 + BK32 + acolf + 8);
            pa3 = *(const float4*)(Ab + (size_t)arow * D_MODEL + k0 + BK32 + acolf + 12);
            pb0 = *(const uint4*)(Bb + (size_t)((k0 + BK32) / 2 + brow) * D_MODEL + bcolw);
            pb1 = *(const uint4*)(Bb + (size_t)((k0 + BK32) / 2 + brow) * D_MODEL + bcolw + 4);
        }

#pragma unroll
        for (int s = 0; s < 2; s++) {
            uint32_t af[4][4];
#pragma unroll
            for (int mt = 0; mt < 4; mt++) {
                const uint32_t* ap = As + (wm + mt * 16 + g) * PAW + s * 8 + t;
                af[mt][0] = ap[0];
                af[mt][1] = ap[8 * PAW];
                af[mt][2] = ap[4];
                af[mt][3] = ap[8 * PAW + 4];
            }
            uint32_t bf[4][2];
#pragma unroll
            for (int nt = 0; nt < 4; nt++) {
                bf[nt][0] = Bs[(s * 8 + t) * PBW + wn + nt * 8 + g];
                bf[nt][1] = Bs[(s * 8 + t + 4) * PBW + wn + nt * 8 + g];
            }
#pragma unroll
            for (int mt = 0; mt < 4; mt++)
#pragma unroll
                for (int nt = 0; nt < 4; nt++)
                    mma_f16(acc[mt][nt], af[mt], bf[nt][0], bf[nt][1]);
        }
        __syncthreads();
    }

    // epilogue: bias + store
#pragma unroll
    for (int mt = 0; mt < 4; mt++) {
        int row0 = by * BM + wm + mt * 16 + g;
#pragma unroll
        for (int nt = 0; nt < 4; nt++) {
            int col = bx * BN + wn + nt * 8 + 2 * t;
            float b0 = bias[col], b1 = bias[col + 1];
            float2 r0 = make_float2(acc[mt][nt][0] + b0, acc[mt][nt][1] + b1);
            float2 r1 = make_float2(acc[mt][nt][2] + b0, acc[mt][nt][3] + b1);
            *(float2*)(C + (size_t)row0 * D_MODEL + col) = r0;
            *(float2*)(C + (size_t)(row0 + 8) * D_MODEL + col) = r1;
        }
    }
}

// ---------------------------------------------------------------------------
// Flash attention, fp16 A-side-split MMA — exact R10-proven version.
// ---------------------------------------------------------------------------
#define OFF_QH 0
#define OFF_QL (64 * PB)
#define OFF_KH (2 * 64 * PB)
#define OFF_VH (3 * 64 * PB)
#define ATT_SMEM (4 * 64 * PB * 2)   // 36864 bytes

__global__ __launch_bounds__(128, 3)
void attention_f16_kernel(const float* __restrict__ Q, const float* __restrict__ K,
                          const float* __restrict__ V, float* __restrict__ O)
{
    extern __shared__ __align__(16) __half sh[];
    __half* Qh = sh + OFF_QH;
    __half* Ql = sh + OFF_QL;
    __half* Kh = sh + OFF_KH;
    __half* Vh = sh + OFF_VH;   // transposed [d][key]

    const uint32_t* Qh32 = (const uint32_t*)Qh;
    const uint32_t* Ql32 = (const uint32_t*)Ql;
    const uint32_t* Kh32 = (const uint32_t*)Kh;
    const uint32_t* Vh32 = (const uint32_t*)Vh;

    const int tid  = threadIdx.x;
    const int warp = tid >> 5, lane = tid & 31;
    const int g = lane >> 2, t = lane & 3;
    const int row16 = warp * 16;

    const int qt = blockIdx.x, h = blockIdx.y, b = blockIdx.z;
    const size_t base = ((size_t)b * TSEQ) * D_MODEL + (size_t)h * HD;
    const float* Qb = Q + base + (size_t)qt * 64 * D_MODEL;
    const float* Kb = K + base;
    const float* Vb = V + base;

    // ---- Load + scale + split Q once (64x64) ----
#pragma unroll
    for (int it = 0; it < 8; it++) {
        int i = tid + it * 128;
        int r = i >> 4, c = (i & 15) * 4;
        float4 q4 = *(const float4*)(Qb + (size_t)r * D_MODEL + c);
        __half h0, h1, h2, h3, l0, l1, l2, l3;
        hsplit(q4.x * 0.125f, h0, l0); hsplit(q4.y * 0.125f, h1, l1);
        hsplit(q4.z * 0.125f, h2, l2); hsplit(q4.w * 0.125f, h3, l3);
        *(uint32_t*)&Qh[r * PB + c]     = pack2h(h0, h1);
        *(uint32_t*)&Qh[r * PB + c + 2] = pack2h(h2, h3);
        *(uint32_t*)&Ql[r * PB + c]     = pack2h(l0, l1);
        *(uint32_t*)&Ql[r * PB + c + 2] = pack2h(l2, l3);
    }
    __syncthreads();

    // ---- Hoist Q fragments to registers (loop-invariant) ----
    uint32_t qfh[4][4], qfl[4][4];
#pragma unroll
    for (int u = 0; u < 4; u++) {
        const int w0 = u * 8 + t;
        qfh[u][0] = Qh32[(row16 + g) * PB32 + w0];
        qfh[u][1] = Qh32[(row16 + g + 8) * PB32 + w0];
        qfh[u][2] = Qh32[(row16 + g) * PB32 + w0 + 4];
        qfh[u][3] = Qh32[(row16 + g + 8) * PB32 + w0 + 4];
        qfl[u][0] = Ql32[(row16 + g) * PB32 + w0];
        qfl[u][1] = Ql32[(row16 + g + 8) * PB32 + w0];
        qfl[u][2] = Ql32[(row16 + g) * PB32 + w0 + 4];
        qfl[u][3] = Ql32[(row16 + g + 8) * PB32 + w0 + 4];
    }

    float oacc[8][4];
#pragma unroll
    for (int j = 0; j < 8; j++)
#pragma unroll
        for (int i = 0; i < 4; i++) oacc[j][i] = 0.f;
    float m0 = -1e30f, m1 = -1e30f, l0s = 0.f, l1s = 0.f;

    const int vrow = row16 + (lane & 15);
    const int vcg  = lane >> 4;

    for (int j0 = 0; j0 < TSEQ; j0 += 64) {
        __syncthreads();  // previous tile's K/V reads complete

        // ---- Load K (coalesced, fp16 hi), V (transposed, fp16 hi) ----
#pragma unroll
        for (int it = 0; it < 8; it++) {
            int i = tid + it * 128;
            int r = i >> 4, c = (i & 15) * 4;
            float4 k4 = *(const float4*)(Kb + (size_t)(j0 + r) * D_MODEL + c);
            *(uint32_t*)&Kh[r * PB + c]     = pack2h(__float2half_rn(k4.x), __float2half_rn(k4.y));
            *(uint32_t*)&Kh[r * PB + c + 2] = pack2h(__float2half_rn(k4.z), __float2half_rn(k4.w));
        }
#pragma unroll
        for (int it = 0; it < 8; it++) {
            int c = (vcg + 2 * it) * 4;
            float4 v4 = *(const float4*)(Vb + (size_t)(j0 + vrow) * D_MODEL + c);
            Vh[(c + 0) * PB + vrow] = __float2half_rn(v4.x);
            Vh[(c + 1) * PB + vrow] = __float2half_rn(v4.y);
            Vh[(c + 2) * PB + vrow] = __float2half_rn(v4.z);
            Vh[(c + 3) * PB + vrow] = __float2half_rn(v4.w);
        }
        __syncthreads();

        // ---- S = (Qh + Ql) Kh^T ----
        float sacc[8][4];
#pragma unroll
        for (int j = 0; j < 8; j++)
#pragma unroll
            for (int i = 0; i < 4; i++) sacc[j][i] = 0.f;

#pragma unroll
        for (int u = 0; u < 4; u++) {
            const int w0 = u * 8 + t;
#pragma unroll
            for (int j = 0; j < 8; j++) {
                uint32_t kh0 = Kh32[(j * 8 + g) * PB32 + w0];
                uint32_t kh1 = Kh32[(j * 8 + g) * PB32 + w0 + 4];
                mma_f16(sacc[j], qfh[u], kh0, kh1);
                mma_f16(sacc[j], qfl[u], kh0, kh1);
            }
        }

        // ---- Online softmax on fragments (rows g and g+8) ----
        float mx0 = -1e30f, mx1 = -1e30f;
#pragma unroll
        for (int j = 0; j < 8; j++) {
            mx0 = fmaxf(mx0, fmaxf(sacc[j][0], sacc[j][1]));
            mx1 = fmaxf(mx1, fmaxf(sacc[j][2], sacc[j][3]));
        }
        mx0 = fmaxf(mx0, __shfl_xor_sync(0xffffffffu, mx0, 1));
        mx0 = fmaxf(mx0, __shfl_xor_sync(0xffffffffu, mx0, 2));
        mx1 = fmaxf(mx1, __shfl_xor_sync(0xffffffffu, mx1, 1));
        mx1 = fmaxf(mx1, __shfl_xor_sync(0xffffffffu, mx1, 2));

        float mn0 = fmaxf(m0, mx0), mn1 = fmaxf(m1, mx1);
        float fac0 = __expf(m0 - mn0), fac1 = __expf(m1 - mn1);
        m0 = mn0; m1 = mn1;

        uint32_t ph01[8], ph23[8], pl01[8], pl23[8];
        float rs0 = 0.f, rs1 = 0.f;
#pragma unroll
        for (int j = 0; j < 8; j++) {
            float p0 = __expf(sacc[j][0] - mn0);
            float p1 = __expf(sacc[j][1] - mn0);
            float p2 = __expf(sacc[j][2] - mn1);
            float p3 = __expf(sacc[j][3] - mn1);
            rs0 += p0 + p1; rs1 += p2 + p3;
            __half h0, h1, h2, h3, q0, q1, q2, q3;
            hsplit(p0, h0, q0); hsplit(p1, h1, q1);
            hsplit(p2, h2, q2); hsplit(p3, h3, q3);
            ph01[j] = pack2h(h0, h1);
            ph23[j] = pack2h(h2, h3);
            pl01[j] = pack2h(q0, q1);
            pl23[j] = pack2h(q2, q3);
        }
        rs0 += __shfl_xor_sync(0xffffffffu, rs0, 1);
        rs0 += __shfl_xor_sync(0xffffffffu, rs0, 2);
        rs1 += __shfl_xor_sync(0xffffffffu, rs1, 1);
        rs1 += __shfl_xor_sync(0xffffffffu, rs1, 2);
        l0s = l0s * fac0 + rs0;
        l1s = l1s * fac1 + rs1;
#pragma unroll
        for (int j = 0; j < 8; j++) {
            oacc[j][0] *= fac0; oacc[j][1] *= fac0;
            oacc[j][2] *= fac1; oacc[j][3] *= fac1;
        }

        // ---- O += (Ph + Pl) Vh, P from registers ----
#pragma unroll
        for (int u = 0; u < 4; u++) {
            const int w0 = u * 8 + t;
            uint32_t pfh[4] = { ph01[2 * u], ph23[2 * u], ph01[2 * u + 1], ph23[2 * u + 1] };
            uint32_t pfl[4] = { pl01[2 * u], pl23[2 * u], pl01[2 * u + 1], pl23[2 * u + 1] };
#pragma unroll
            for (int j = 0; j < 8; j++) {
                uint32_t vh0 = Vh32[(j * 8 + g) * PB32 + w0];
                uint32_t vh1 = Vh32[(j * 8 + g) * PB32 + w0 + 4];
                mma_f16(oacc[j], pfh, vh0, vh1);
                mma_f16(oacc[j], pfl, vh0, vh1);
            }
        }
    }

    // ---- Epilogue: normalize, store ----
    float inv0 = 1.f / l0s, inv1 = 1.f / l1s;
    float* Ob = O + base + (size_t)qt * 64 * D_MODEL;
#pragma unroll
    for (int j = 0; j < 8; j++) {
        int col = j * 8 + 2 * t;
        *(float2*)(Ob + (size_t)(row16 + g) * D_MODEL + col) =
            make_float2(oacc[j][0] * inv0, oacc[j][1] * inv0);
        *(float2*)(Ob + (size_t)(row16 + g + 8) * D_MODEL + col) =
            make_float2(oacc[j][2] * inv1, oacc[j][3] * inv1);
    }
}

// ---------------------------------------------------------------------------
// Launch. Input order:
// 0:q 1:k 2:v 3:W_q 4:b_q 5:W_k 6:b_k 7:W_v 8:b_v 9:W_o 10:b_o
// ---------------------------------------------------------------------------
extern "C" void kernel_launch(void* const* d_in, const int* in_sizes, int n_in,
                              void* d_out, int out_size)
{
    (void)in_sizes; (void)n_in; (void)out_size;
    const float* q   = (const float*)d_in[0];
    const float* k   = (const float*)d_in[1];
    const float* v   = (const float*)d_in[2];
    const float* W_q = (const float*)d_in[3];
    const float* b_q = (const float*)d_in[4];
    const float* W_k = (const float*)d_in[5];
    const float* b_k = (const float*)d_in[6];
    const float* W_v = (const float*)d_in[7];
    const float* b_v = (const float*)d_in[8];
    const float* W_o = (const float*)d_in[9];
    const float* b_o = (const float*)d_in[10];
    float* out = (float*)d_out;

    float *gQ, *gK, *gV, *gA;
    uint32_t* gW;
    cudaGetSymbolAddress((void**)&gQ, g_Q);
    cudaGetSymbolAddress((void**)&gK, g_K);
    cudaGetSymbolAddress((void**)&gV, g_V);
    cudaGetSymbolAddress((void**)&gA, g_A);
    cudaGetSymbolAddress((void**)&gW, g_W16);
    const int WSTRIDE = (D_MODEL / 2) * D_MODEL;

    // Pre-pack all 4 weight matrices to fp16 k-pair layout (~4 us)
    pack_w16_kernel<<<dim3((D_MODEL / 2) * D_MODEL / 256, 4), 256>>>(W_q, W_k, W_v, W_o);

    dim3 gridP(D_MODEL / BN, NTOK / BM);  // (8, 64)

    gemm_f16_bias<<<gridP, 256>>>(q, gW + 0 * WSTRIDE, b_q, gQ);
    gemm_f16_bias<<<gridP, 256>>>(k, gW + 1 * WSTRIDE, b_k, gK);
    gemm_f16_bias<<<gridP, 256>>>(v, gW + 2 * WSTRIDE, b_v, gV);

    cudaFuncSetAttribute(attention_f16_kernel,
                         cudaFuncAttributeMaxDynamicSharedMemorySize, ATT_SMEM);
    attention_f16_kernel<<<dim3(TSEQ / 64, HEADS, BATCH), 128, ATT_SMEM>>>(gQ, gK, gV, gA);

    gemm_f16_bias<<<gridP, 256>>>(gA, gW + 3 * WSTRIDE, b_o, out);
}

// round 13
// speedup vs baseline: 1.3282x; 1.3282x over previous
#include <cuda_runtime.h>
#include <cuda_fp16.h>
#include <math.h>
#include <stdint.h>
#include <string.h>

#define D_MODEL 1024
#define NTOK    8192   // B*T
#define HEADS   16
#define HD      64
#define TSEQ    2048
#define BATCH   4

// GEMM tiling (tf32, proven)
#define BM 128
#define BN 128
#define BKT 16
#define APAD 20
#define BPAD 136

// Attention fp16 smem pitch (fp16 elements). 72*2B=144B rows; 36 words.
#define PB   72
#define PB32 36

// Scratch (no allocation allowed — device globals). 16B-aligned.
__device__ __align__(16) float g_Q[NTOK * D_MODEL];
__device__ __align__(16) float g_K[NTOK * D_MODEL];
__device__ __align__(16) float g_V[NTOK * D_MODEL];
__device__ __align__(16) float g_A[NTOK * D_MODEL];

__device__ __forceinline__ float tf32r(float x) {
    uint32_t u;
    asm("cvt.rna.tf32.f32 %0, %1;" : "=r"(u) : "f"(x));
    return __uint_as_float(u);
}

__device__ __forceinline__ void mma_tf32(float* c, const uint32_t* a, const uint32_t* b) {
    asm volatile(
        "mma.sync.aligned.m16n8k8.row.col.f32.tf32.tf32.f32 "
        "{%0,%1,%2,%3}, {%4,%5,%6,%7}, {%8,%9}, {%0,%1,%2,%3};\n"
        : "+f"(c[0]), "+f"(c[1]), "+f"(c[2]), "+f"(c[3])
        : "r"(a[0]), "r"(a[1]), "r"(a[2]), "r"(a[3]), "r"(b[0]), "r"(b[1]));
}

__device__ __forceinline__ void mma_f16(float* c, const uint32_t* a, uint32_t b0, uint32_t b1) {
    asm volatile(
        "mma.sync.aligned.m16n8k16.row.col.f32.f16.f16.f32 "
        "{%0,%1,%2,%3}, {%4,%5,%6,%7}, {%8,%9}, {%0,%1,%2,%3};\n"
        : "+f"(c[0]), "+f"(c[1]), "+f"(c[2]), "+f"(c[3])
        : "r"(a[0]), "r"(a[1]), "r"(a[2]), "r"(a[3]), "r"(b0), "r"(b1));
}

// split fp32 -> fp16 hi + fp16 lo (hi+lo reproduces ~22 mantissa bits)
__device__ __forceinline__ void hsplit(float x, __half& h, __half& l) {
    h = __float2half_rn(x);
    l = __float2half_rn(x - __half2float(h));
}

// pack two fp16 into one 32-bit word (lo -> low half)
__device__ __forceinline__ uint32_t pack2h(__half lo, __half hi) {
    __half2 p = __halves2half2(lo, hi);
    uint32_t u;
    memcpy(&u, &p, 4);
    return u;
}

// ---------------------------------------------------------------------------
// TF32 tensor-core GEMM body — exact R10-proven single-buffer version.
// ---------------------------------------------------------------------------
__device__ __forceinline__
void gemm_tf32_body(const float* __restrict__ A, const float* __restrict__ B,
                    const float* __restrict__ bias, float* __restrict__ C,
                    int M, int N, int K)
{
    __shared__ float As[BM * APAD];
    __shared__ float Bs[BKT * BPAD];

    const int tid  = threadIdx.x;
    const int warp = tid >> 5, lane = tid & 31;
    const int g = lane >> 2, t = lane & 3;
    const int wm = (warp >> 2) * 64;
    const int wn = (warp & 3) * 32;

    const int bx = blockIdx.x, by = blockIdx.y;
    const float* Ab = A + (size_t)by * BM * K;
    const float* Bb = B + bx * BN;

    const int arow = tid >> 1, acol = (tid & 1) * 8;
    const int brow = tid >> 4, bcol = (tid & 15) * 8;

    float4 pa0 = *(const float4*)(Ab + (size_t)arow * K + acol);
    float4 pa1 = *(const float4*)(Ab + (size_t)arow * K + acol + 4);
    float4 pb0 = *(const float4*)(Bb + (size_t)brow * N + bcol);
    float4 pb1 = *(const float4*)(Bb + (size_t)brow * N + bcol + 4);

    float acc[4][4][4];
#pragma unroll
    for (int mt = 0; mt < 4; mt++)
#pragma unroll
        for (int nt = 0; nt < 4; nt++)
#pragma unroll
            for (int i = 0; i < 4; i++) acc[mt][nt][i] = 0.f;

    for (int k0 = 0; k0 < K; k0 += BKT) {
        float* ad = As + arow * APAD + acol;
        ad[0] = tf32r(pa0.x); ad[1] = tf32r(pa0.y); ad[2] = tf32r(pa0.z); ad[3] = tf32r(pa0.w);
        ad[4] = tf32r(pa1.x); ad[5] = tf32r(pa1.y); ad[6] = tf32r(pa1.z); ad[7] = tf32r(pa1.w);
        float* bd = Bs + brow * BPAD + bcol;
        bd[0] = tf32r(pb0.x); bd[1] = tf32r(pb0.y); bd[2] = tf32r(pb0.z); bd[3] = tf32r(pb0.w);
        bd[4] = tf32r(pb1.x); bd[5] = tf32r(pb1.y); bd[6] = tf32r(pb1.z); bd[7] = tf32r(pb1.w);
        __syncthreads();

        if (k0 + BKT < K) {
            pa0 = *(const float4*)(Ab + (size_t)arow * K + k0 + BKT + acol);
            pa1 = *(const float4*)(Ab + (size_t)arow * K + k0 + BKT + acol + 4);
            pb0 = *(const float4*)(Bb + (size_t)(k0 + BKT + brow) * N + bcol);
            pb1 = *(const float4*)(Bb + (size_t)(k0 + BKT + brow) * N + bcol + 4);
        }

#pragma unroll
        for (int kk = 0; kk < BKT; kk += 8) {
            uint32_t af[4][4];
#pragma unroll
            for (int mt = 0; mt < 4; mt++) {
                const float* ap = As + (wm + mt * 16 + g) * APAD + kk + t;
                af[mt][0] = __float_as_uint(ap[0]);
                af[mt][1] = __float_as_uint(ap[8 * APAD]);
                af[mt][2] = __float_as_uint(ap[4]);
                af[mt][3] = __float_as_uint(ap[8 * APAD + 4]);
            }
            uint32_t bf[4][2];
#pragma unroll
            for (int nt = 0; nt < 4; nt++) {
                const float* bp = Bs + (kk + t) * BPAD + wn + nt * 8 + g;
                bf[nt][0] = __float_as_uint(bp[0]);
                bf[nt][1] = __float_as_uint(bp[4 * BPAD]);
            }
#pragma unroll
            for (int mt = 0; mt < 4; mt++)
#pragma unroll
                for (int nt = 0; nt < 4; nt++)
                    mma_tf32(acc[mt][nt], af[mt], bf[nt]);
        }
        __syncthreads();
    }

#pragma unroll
    for (int mt = 0; mt < 4; mt++) {
        int row0 = by * BM + wm + mt * 16 + g;
#pragma unroll
        for (int nt = 0; nt < 4; nt++) {
            int col = bx * BN + wn + nt * 8 + 2 * t;
            float b0 = bias[col], b1 = bias[col + 1];
            float2 r0 = make_float2(acc[mt][nt][0] + b0, acc[mt][nt][1] + b1);
            float2 r1 = make_float2(acc[mt][nt][2] + b0, acc[mt][nt][3] + b1);
            *(float2*)(C + (size_t)row0 * N + col) = r0;
            *(float2*)(C + (size_t)(row0 + 8) * N + col) = r1;
        }
    }
}

// Fused Q/K/V projections: blockIdx.z selects input/weight/bias/output.
__global__ __launch_bounds__(256, 2)
void gemm_qkv_kernel(const float* __restrict__ q, const float* __restrict__ k,
                     const float* __restrict__ v,
                     const float* __restrict__ Wq, const float* __restrict__ Wk,
                     const float* __restrict__ Wv,
                     const float* __restrict__ bq, const float* __restrict__ bk,
                     const float* __restrict__ bv,
                     float* __restrict__ Cq, float* __restrict__ Ck,
                     float* __restrict__ Cv)
{
    const int z = blockIdx.z;
    const float* A = (z == 0) ? q : (z == 1) ? k : v;
    const float* B = (z == 0) ? Wq : (z == 1) ? Wk : Wv;
    const float* bias = (z == 0) ? bq : (z == 1) ? bk : bv;
    float* C = (z == 0) ? Cq : (z == 1) ? Ck : Cv;
    gemm_tf32_body(A, B, bias, C, NTOK, D_MODEL, D_MODEL);
}

__global__ __launch_bounds__(256, 2)
void gemm_o_kernel(const float* __restrict__ A, const float* __restrict__ B,
                   const float* __restrict__ bias, float* __restrict__ C)
{
    gemm_tf32_body(A, B, bias, C, NTOK, D_MODEL, D_MODEL);
}

// ---------------------------------------------------------------------------
// Flash attention, fp16 A-side-split MMA — exact R10-proven version.
// ---------------------------------------------------------------------------
#define OFF_QH 0
#define OFF_QL (64 * PB)
#define OFF_KH (2 * 64 * PB)
#define OFF_VH (3 * 64 * PB)
#define ATT_SMEM (4 * 64 * PB * 2)   // 36864 bytes

__global__ __launch_bounds__(128, 3)
void attention_f16_kernel(const float* __restrict__ Q, const float* __restrict__ K,
                          const float* __restrict__ V, float* __restrict__ O)
{
    extern __shared__ __align__(16) __half sh[];
    __half* Qh = sh + OFF_QH;
    __half* Ql = sh + OFF_QL;
    __half* Kh = sh + OFF_KH;
    __half* Vh = sh + OFF_VH;   // transposed [d][key]

    const uint32_t* Qh32 = (const uint32_t*)Qh;
    const uint32_t* Ql32 = (const uint32_t*)Ql;
    const uint32_t* Kh32 = (const uint32_t*)Kh;
    const uint32_t* Vh32 = (const uint32_t*)Vh;

    const int tid  = threadIdx.x;
    const int warp = tid >> 5, lane = tid & 31;
    const int g = lane >> 2, t = lane & 3;
    const int row16 = warp * 16;

    const int qt = blockIdx.x, h = blockIdx.y, b = blockIdx.z;
    const size_t base = ((size_t)b * TSEQ) * D_MODEL + (size_t)h * HD;
    const float* Qb = Q + base + (size_t)qt * 64 * D_MODEL;
    const float* Kb = K + base;
    const float* Vb = V + base;

    // ---- Load + scale + split Q once (64x64) ----
#pragma unroll
    for (int it = 0; it < 8; it++) {
        int i = tid + it * 128;
        int r = i >> 4, c = (i & 15) * 4;
        float4 q4 = *(const float4*)(Qb + (size_t)r * D_MODEL + c);
        __half h0, h1, h2, h3, l0, l1, l2, l3;
        hsplit(q4.x * 0.125f, h0, l0); hsplit(q4.y * 0.125f, h1, l1);
        hsplit(q4.z * 0.125f, h2, l2); hsplit(q4.w * 0.125f, h3, l3);
        *(uint32_t*)&Qh[r * PB + c]     = pack2h(h0, h1);
        *(uint32_t*)&Qh[r * PB + c + 2] = pack2h(h2, h3);
        *(uint32_t*)&Ql[r * PB + c]     = pack2h(l0, l1);
        *(uint32_t*)&Ql[r * PB + c + 2] = pack2h(l2, l3);
    }
    __syncthreads();

    // ---- Hoist Q fragments to registers (loop-invariant) ----
    uint32_t qfh[4][4], qfl[4][4];
#pragma unroll
    for (int u = 0; u < 4; u++) {
        const int w0 = u * 8 + t;
        qfh[u][0] = Qh32[(row16 + g) * PB32 + w0];
        qfh[u][1] = Qh32[(row16 + g + 8) * PB32 + w0];
        qfh[u][2] = Qh32[(row16 + g) * PB32 + w0 + 4];
        qfh[u][3] = Qh32[(row16 + g + 8) * PB32 + w0 + 4];
        qfl[u][0] = Ql32[(row16 + g) * PB32 + w0];
        qfl[u][1] = Ql32[(row16 + g + 8) * PB32 + w0];
        qfl[u][2] = Ql32[(row16 + g) * PB32 + w0 + 4];
        qfl[u][3] = Ql32[(row16 + g + 8) * PB32 + w0 + 4];
    }

    float oacc[8][4];
#pragma unroll
    for (int j = 0; j < 8; j++)
#pragma unroll
        for (int i = 0; i < 4; i++) oacc[j][i] = 0.f;
    float m0 = -1e30f, m1 = -1e30f, l0s = 0.f, l1s = 0.f;

    const int vrow = row16 + (lane & 15);
    const int vcg  = lane >> 4;

    for (int j0 = 0; j0 < TSEQ; j0 += 64) {
        __syncthreads();  // previous tile's K/V reads complete

        // ---- Load K (coalesced, fp16 hi), V (transposed, fp16 hi) ----
#pragma unroll
        for (int it = 0; it < 8; it++) {
            int i = tid + it * 128;
            int r = i >> 4, c = (i & 15) * 4;
            float4 k4 = *(const float4*)(Kb + (size_t)(j0 + r) * D_MODEL + c);
            *(uint32_t*)&Kh[r * PB + c]     = pack2h(__float2half_rn(k4.x), __float2half_rn(k4.y));
            *(uint32_t*)&Kh[r * PB + c + 2] = pack2h(__float2half_rn(k4.z), __float2half_rn(k4.w));
        }
#pragma unroll
        for (int it = 0; it < 8; it++) {
            int c = (vcg + 2 * it) * 4;
            float4 v4 = *(const float4*)(Vb + (size_t)(j0 + vrow) * D_MODEL + c);
            Vh[(c + 0) * PB + vrow] = __float2half_rn(v4.x);
            Vh[(c + 1) * PB + vrow] = __float2half_rn(v4.y);
            Vh[(c + 2) * PB + vrow] = __float2half_rn(v4.z);
            Vh[(c + 3) * PB + vrow] = __float2half_rn(v4.w);
        }
        __syncthreads();

        // ---- S = (Qh + Ql) Kh^T ----
        float sacc[8][4];
#pragma unroll
        for (int j = 0; j < 8; j++)
#pragma unroll
            for (int i = 0; i < 4; i++) sacc[j][i] = 0.f;

#pragma unroll
        for (int u = 0; u < 4; u++) {
            const int w0 = u * 8 + t;
#pragma unroll
            for (int j = 0; j < 8; j++) {
                uint32_t kh0 = Kh32[(j * 8 + g) * PB32 + w0];
                uint32_t kh1 = Kh32[(j * 8 + g) * PB32 + w0 + 4];
                mma_f16(sacc[j], qfh[u], kh0, kh1);
                mma_f16(sacc[j], qfl[u], kh0, kh1);
            }
        }

        // ---- Online softmax on fragments (rows g and g+8) ----
        float mx0 = -1e30f, mx1 = -1e30f;
#pragma unroll
        for (int j = 0; j < 8; j++) {
            mx0 = fmaxf(mx0, fmaxf(sacc[j][0], sacc[j][1]));
            mx1 = fmaxf(mx1, fmaxf(sacc[j][2], sacc[j][3]));
        }
        mx0 = fmaxf(mx0, __shfl_xor_sync(0xffffffffu, mx0, 1));
        mx0 = fmaxf(mx0, __shfl_xor_sync(0xffffffffu, mx0, 2));
        mx1 = fmaxf(mx1, __shfl_xor_sync(0xffffffffu, mx1, 1));
        mx1 = fmaxf(mx1, __shfl_xor_sync(0xffffffffu, mx1, 2));

        float mn0 = fmaxf(m0, mx0), mn1 = fmaxf(m1, mx1);
        float fac0 = __expf(m0 - mn0), fac1 = __expf(m1 - mn1);
        m0 = mn0; m1 = mn1;

        uint32_t ph01[8], ph23[8], pl01[8], pl23[8];
        float rs0 = 0.f, rs1 = 0.f;
#pragma unroll
        for (int j = 0; j < 8; j++) {
            float p0 = __expf(sacc[j][0] - mn0);
            float p1 = __expf(sacc[j][1] - mn0);
            float p2 = __expf(sacc[j][2] - mn1);
            float p3 = __expf(sacc[j][3] - mn1);
            rs0 += p0 + p1; rs1 += p2 + p3;
            __half h0, h1, h2, h3, q0, q1, q2, q3;
            hsplit(p0, h0, q0); hsplit(p1, h1, q1);
            hsplit(p2, h2, q2); hsplit(p3, h3, q3);
            ph01[j] = pack2h(h0, h1);
            ph23[j] = pack2h(h2, h3);
            pl01[j] = pack2h(q0, q1);
            pl23[j] = pack2h(q2, q3);
        }
        rs0 += __shfl_xor_sync(0xffffffffu, rs0, 1);
        rs0 += __shfl_xor_sync(0xffffffffu, rs0, 2);
        rs1 += __shfl_xor_sync(0xffffffffu, rs1, 1);
        rs1 += __shfl_xor_sync(0xffffffffu, rs1, 2);
        l0s = l0s * fac0 + rs0;
        l1s = l1s * fac1 + rs1;
#pragma unroll
        for (int j = 0; j < 8; j++) {
            oacc[j][0] *= fac0; oacc[j][1] *= fac0;
            oacc[j][2] *= fac1; oacc[j][3] *= fac1;
        }

        // ---- O += (Ph + Pl) Vh, P from registers ----
#pragma unroll
        for (int u = 0; u < 4; u++) {
            const int w0 = u * 8 + t;
            uint32_t pfh[4] = { ph01[2 * u], ph23[2 * u], ph01[2 * u + 1], ph23[2 * u + 1] };
            uint32_t pfl[4] = { pl01[2 * u], pl23[2 * u], pl01[2 * u + 1], pl23[2 * u + 1] };
#pragma unroll
            for (int j = 0; j < 8; j++) {
                uint32_t vh0 = Vh32[(j * 8 + g) * PB32 + w0];
                uint32_t vh1 = Vh32[(j * 8 + g) * PB32 + w0 + 4];
                mma_f16(oacc[j], pfh, vh0, vh1);
                mma_f16(oacc[j], pfl, vh0, vh1);
            }
        }
    }

    // ---- Epilogue: normalize, store ----
    float inv0 = 1.f / l0s, inv1 = 1.f / l1s;
    float* Ob = O + base + (size_t)qt * 64 * D_MODEL;
#pragma unroll
    for (int j = 0; j < 8; j++) {
        int col = j * 8 + 2 * t;
        *(float2*)(Ob + (size_t)(row16 + g) * D_MODEL + col) =
            make_float2(oacc[j][0] * inv0, oacc[j][1] * inv0);
        *(float2*)(Ob + (size_t)(row16 + g + 8) * D_MODEL + col) =
            make_float2(oacc[j][2] * inv1, oacc[j][3] * inv1);
    }
}

// ---------------------------------------------------------------------------
// Launch. Input order:
// 0:q 1:k 2:v 3:W_q 4:b_q 5:W_k 6:b_k 7:W_v 8:b_v 9:W_o 10:b_o
// ---------------------------------------------------------------------------
extern "C" void kernel_launch(void* const* d_in, const int* in_sizes, int n_in,
                              void* d_out, int out_size)
{
    (void)in_sizes; (void)n_in; (void)out_size;
    const float* q   = (const float*)d_in[0];
    const float* k   = (const float*)d_in[1];
    const float* v   = (const float*)d_in[2];
    const float* W_q = (const float*)d_in[3];
    const float* b_q = (const float*)d_in[4];
    const float* W_k = (const float*)d_in[5];
    const float* b_k = (const float*)d_in[6];
    const float* W_v = (const float*)d_in[7];
    const float* b_v = (const float*)d_in[8];
    const float* W_o = (const float*)d_in[9];
    const float* b_o = (const float*)d_in[10];
    float* out = (float*)d_out;

    float *gQ, *gK, *gV, *gA;
    cudaGetSymbolAddress((void**)&gQ, g_Q);
    cudaGetSymbolAddress((void**)&gK, g_K);
    cudaGetSymbolAddress((void**)&gV, g_V);
    cudaGetSymbolAddress((void**)&gA, g_A);

    // Fused Q/K/V projections: one launch, 1536 blocks, proven GEMM body.
    gemm_qkv_kernel<<<dim3(D_MODEL / BN, NTOK / BM, 3), 256>>>(
        q, k, v, W_q, W_k, W_v, b_q, b_k, b_v, gQ, gK, gV);

    cudaFuncSetAttribute(attention_f16_kernel,
                         cudaFuncAttributeMaxDynamicSharedMemorySize, ATT_SMEM);
    attention_f16_kernel<<<dim3(TSEQ / 64, HEADS, BATCH), 128, ATT_SMEM>>>(gQ, gK, gV, gA);

    gemm_o_kernel<<<dim3(D_MODEL / BN, NTOK / BM), 256>>>(gA, W_o, b_o, out);
}

// round 14
// speedup vs baseline: 1.4414x; 1.0852x over previous
#include <cuda_runtime.h>
#include <cuda_fp16.h>
#include <math.h>
#include <stdint.h>
#include <string.h>

#define D_MODEL 1024
#define NTOK    8192   // B*T
#define HEADS   16
#define HD      64
#define TSEQ    2048
#define BATCH   4

// GEMM tiling (tf32, proven)
#define BM 128
#define BN 128
#define BKT 16
#define APAD 20
#define BPAD 136

// Attention smem pitches
#define PB   72    // fp16 plane pitch (elements); 36 words
#define PB32 36
#define PSG  68    // fp32 staging pitch (floats)

// Scratch (no allocation allowed — device globals). 16B-aligned.
__device__ __align__(16) float g_Q[NTOK * D_MODEL];
__device__ __align__(16) float g_K[NTOK * D_MODEL];
__device__ __align__(16) float g_V[NTOK * D_MODEL];
__device__ __align__(16) float g_A[NTOK * D_MODEL];

__device__ __forceinline__ float tf32r(float x) {
    uint32_t u;
    asm("cvt.rna.tf32.f32 %0, %1;" : "=r"(u) : "f"(x));
    return __uint_as_float(u);
}

__device__ __forceinline__ void mma_tf32(float* c, const uint32_t* a, const uint32_t* b) {
    asm volatile(
        "mma.sync.aligned.m16n8k8.row.col.f32.tf32.tf32.f32 "
        "{%0,%1,%2,%3}, {%4,%5,%6,%7}, {%8,%9}, {%0,%1,%2,%3};\n"
        : "+f"(c[0]), "+f"(c[1]), "+f"(c[2]), "+f"(c[3])
        : "r"(a[0]), "r"(a[1]), "r"(a[2]), "r"(a[3]), "r"(b[0]), "r"(b[1]));
}

__device__ __forceinline__ void mma_f16(float* c, const uint32_t* a, uint32_t b0, uint32_t b1) {
    asm volatile(
        "mma.sync.aligned.m16n8k16.row.col.f32.f16.f16.f32 "
        "{%0,%1,%2,%3}, {%4,%5,%6,%7}, {%8,%9}, {%0,%1,%2,%3};\n"
        : "+f"(c[0]), "+f"(c[1]), "+f"(c[2]), "+f"(c[3])
        : "r"(a[0]), "r"(a[1]), "r"(a[2]), "r"(a[3]), "r"(b0), "r"(b1));
}

// split fp32 -> fp16 hi + fp16 lo (hi+lo reproduces ~22 mantissa bits)
__device__ __forceinline__ void hsplit(float x, __half& h, __half& l) {
    h = __float2half_rn(x);
    l = __float2half_rn(x - __half2float(h));
}

// pack two fp16 into one 32-bit word (lo -> low half)
__device__ __forceinline__ uint32_t pack2h(__half lo, __half hi) {
    __half2 p = __halves2half2(lo, hi);
    uint32_t u;
    memcpy(&u, &p, 4);
    return u;
}

__device__ __forceinline__ uint32_t cvta_smem(const void* p) {
    return (uint32_t)__cvta_generic_to_shared(p);
}

// cp.async 16B (cg: L2-only, streaming)
__device__ __forceinline__ void cp16(uint32_t dst, const void* src) {
    asm volatile("cp.async.cg.shared.global [%0], [%1], 16;" :: "r"(dst), "l"(src));
}
__device__ __forceinline__ void cp_commit() {
    asm volatile("cp.async.commit_group;" ::: "memory");
}
__device__ __forceinline__ void cp_wait0() {
    asm volatile("cp.async.wait_group 0;" ::: "memory");
}

// ---------------------------------------------------------------------------
// TF32 tensor-core GEMM body — exact R12-proven single-buffer version.
// ---------------------------------------------------------------------------
__device__ __forceinline__
void gemm_tf32_body(const float* __restrict__ A, const float* __restrict__ B,
                    const float* __restrict__ bias, float* __restrict__ C,
                    int M, int N, int K)
{
    __shared__ float As[BM * APAD];
    __shared__ float Bs[BKT * BPAD];

    const int tid  = threadIdx.x;
    const int warp = tid >> 5, lane = tid & 31;
    const int g = lane >> 2, t = lane & 3;
    const int wm = (warp >> 2) * 64;
    const int wn = (warp & 3) * 32;

    const int bx = blockIdx.x, by = blockIdx.y;
    const float* Ab = A + (size_t)by * BM * K;
    const float* Bb = B + bx * BN;

    const int arow = tid >> 1, acol = (tid & 1) * 8;
    const int brow = tid >> 4, bcol = (tid & 15) * 8;

    float4 pa0 = *(const float4*)(Ab + (size_t)arow * K + acol);
    float4 pa1 = *(const float4*)(Ab + (size_t)arow * K + acol + 4);
    float4 pb0 = *(const float4*)(Bb + (size_t)brow * N + bcol);
    float4 pb1 = *(const float4*)(Bb + (size_t)brow * N + bcol + 4);

    float acc[4][4][4];
#pragma unroll
    for (int mt = 0; mt < 4; mt++)
#pragma unroll
        for (int nt = 0; nt < 4; nt++)
#pragma unroll
            for (int i = 0; i < 4; i++) acc[mt][nt][i] = 0.f;

    for (int k0 = 0; k0 < K; k0 += BKT) {
        float* ad = As + arow * APAD + acol;
        ad[0] = tf32r(pa0.x); ad[1] = tf32r(pa0.y); ad[2] = tf32r(pa0.z); ad[3] = tf32r(pa0.w);
        ad[4] = tf32r(pa1.x); ad[5] = tf32r(pa1.y); ad[6] = tf32r(pa1.z); ad[7] = tf32r(pa1.w);
        float* bd = Bs + brow * BPAD + bcol;
        bd[0] = tf32r(pb0.x); bd[1] = tf32r(pb0.y); bd[2] = tf32r(pb0.z); bd[3] = tf32r(pb0.w);
        bd[4] = tf32r(pb1.x); bd[5] = tf32r(pb1.y); bd[6] = tf32r(pb1.z); bd[7] = tf32r(pb1.w);
        __syncthreads();

        if (k0 + BKT < K) {
            pa0 = *(const float4*)(Ab + (size_t)arow * K + k0 + BKT + acol);
            pa1 = *(const float4*)(Ab + (size_t)arow * K + k0 + BKT + acol + 4);
            pb0 = *(const float4*)(Bb + (size_t)(k0 + BKT + brow) * N + bcol);
            pb1 = *(const float4*)(Bb + (size_t)(k0 + BKT + brow) * N + bcol + 4);
        }

#pragma unroll
        for (int kk = 0; kk < BKT; kk += 8) {
            uint32_t af[4][4];
#pragma unroll
            for (int mt = 0; mt < 4; mt++) {
                const float* ap = As + (wm + mt * 16 + g) * APAD + kk + t;
                af[mt][0] = __float_as_uint(ap[0]);
                af[mt][1] = __float_as_uint(ap[8 * APAD]);
                af[mt][2] = __float_as_uint(ap[4]);
                af[mt][3] = __float_as_uint(ap[8 * APAD + 4]);
            }
            uint32_t bf[4][2];
#pragma unroll
            for (int nt = 0; nt < 4; nt++) {
                const float* bp = Bs + (kk + t) * BPAD + wn + nt * 8 + g;
                bf[nt][0] = __float_as_uint(bp[0]);
                bf[nt][1] = __float_as_uint(bp[4 * BPAD]);
            }
#pragma unroll
            for (int mt = 0; mt < 4; mt++)
#pragma unroll
                for (int nt = 0; nt < 4; nt++)
                    mma_tf32(acc[mt][nt], af[mt], bf[nt]);
        }
        __syncthreads();
    }

#pragma unroll
    for (int mt = 0; mt < 4; mt++) {
        int row0 = by * BM + wm + mt * 16 + g;
#pragma unroll
        for (int nt = 0; nt < 4; nt++) {
            int col = bx * BN + wn + nt * 8 + 2 * t;
            float b0 = bias[col], b1 = bias[col + 1];
            float2 r0 = make_float2(acc[mt][nt][0] + b0, acc[mt][nt][1] + b1);
            float2 r1 = make_float2(acc[mt][nt][2] + b0, acc[mt][nt][3] + b1);
            *(float2*)(C + (size_t)row0 * N + col) = r0;
            *(float2*)(C + (size_t)(row0 + 8) * N + col) = r1;
        }
    }
}

// Fused Q/K/V projections: blockIdx.z selects input/weight/bias/output.
__global__ __launch_bounds__(256, 2)
void gemm_qkv_kernel(const float* __restrict__ q, const float* __restrict__ k,
                     const float* __restrict__ v,
                     const float* __restrict__ Wq, const float* __restrict__ Wk,
                     const float* __restrict__ Wv,
                     const float* __restrict__ bq, const float* __restrict__ bk,
                     const float* __restrict__ bv,
                     float* __restrict__ Cq, float* __restrict__ Ck,
                     float* __restrict__ Cv)
{
    const int z = blockIdx.z;
    const float* A = (z == 0) ? q : (z == 1) ? k : v;
    const float* B = (z == 0) ? Wq : (z == 1) ? Wk : Wv;
    const float* bias = (z == 0) ? bq : (z == 1) ? bk : bv;
    float* C = (z == 0) ? Cq : (z == 1) ? Ck : Cv;
    gemm_tf32_body(A, B, bias, C, NTOK, D_MODEL, D_MODEL);
}

__global__ __launch_bounds__(256, 2)
void gemm_o_kernel(const float* __restrict__ A, const float* __restrict__ B,
                   const float* __restrict__ bias, float* __restrict__ C)
{
    gemm_tf32_body(A, B, bias, C, NTOK, D_MODEL, D_MODEL);
}

// ---------------------------------------------------------------------------
// Flash attention, fp16 A-side-split MMA + cp.async K/V staging pipeline.
// smem layout (bytes):
//   [0      )  Qh  64x72 fp16   9216
//   [9216   )  Ql                9216
//   [18432  )  Kh                9216
//   [27648  )  Vh (transposed)   9216
//   [36864  )  Ksg 64x68 fp32   17408   (cp.async staging, next tile)
//   [54272  )  Vsg              17408
//   total 71680 -> 3 blocks/SM (215 KB), regs capped at 170.
// ---------------------------------------------------------------------------
#define ATT_SMEM 71680

__global__ __launch_bounds__(128, 3)
void attention_f16_kernel(const float* __restrict__ Q, const float* __restrict__ K,
                          const float* __restrict__ V, float* __restrict__ O)
{
    extern __shared__ __align__(16) char smraw[];
    __half* Qh = (__half*)(smraw);
    __half* Ql = (__half*)(smraw + 9216);
    __half* Kh = (__half*)(smraw + 18432);
    __half* Vh = (__half*)(smraw + 27648);
    float*  Ksg = (float*)(smraw + 36864);
    float*  Vsg = (float*)(smraw + 54272);

    const uint32_t* Qh32 = (const uint32_t*)Qh;
    const uint32_t* Ql32 = (const uint32_t*)Ql;
    const uint32_t* Kh32 = (const uint32_t*)Kh;
    const uint32_t* Vh32 = (const uint32_t*)Vh;

    const uint32_t ksg_s = cvta_smem(Ksg);
    const uint32_t vsg_s = cvta_smem(Vsg);

    const int tid  = threadIdx.x;
    const int warp = tid >> 5, lane = tid & 31;
    const int g = lane >> 2, t = lane & 3;
    const int row16 = warp * 16;

    const int qt = blockIdx.x, h = blockIdx.y, b = blockIdx.z;
    const size_t base = ((size_t)b * TSEQ) * D_MODEL + (size_t)h * HD;
    const float* Qb = Q + base + (size_t)qt * 64 * D_MODEL;
    const float* Kb = K + base;
    const float* Vb = V + base;

    // per-thread cp.async slice: rows (tid>>4)+8*it, col (tid&15)*4 — coalesced
    const int sgc = (tid & 15) * 4;
    const int sgr = tid >> 4;

    // ---- Stage tile 0 K/V (overlaps Q processing) ----
#pragma unroll
    for (int it = 0; it < 8; it++) {
        int r = sgr + 8 * it;
        cp16(ksg_s + (uint32_t)(r * PSG + sgc) * 4, Kb + (size_t)r * D_MODEL + sgc);
        cp16(vsg_s + (uint32_t)(r * PSG + sgc) * 4, Vb + (size_t)r * D_MODEL + sgc);
    }
    cp_commit();

    // ---- Load + scale + split Q once (64x64) ----
#pragma unroll
    for (int it = 0; it < 8; it++) {
        int i = tid + it * 128;
        int r = i >> 4, c = (i & 15) * 4;
        float4 q4 = *(const float4*)(Qb + (size_t)r * D_MODEL + c);
        __half h0, h1, h2, h3, l0, l1, l2, l3;
        hsplit(q4.x * 0.125f, h0, l0); hsplit(q4.y * 0.125f, h1, l1);
        hsplit(q4.z * 0.125f, h2, l2); hsplit(q4.w * 0.125f, h3, l3);
        *(uint32_t*)&Qh[r * PB + c]     = pack2h(h0, h1);
        *(uint32_t*)&Qh[r * PB + c + 2] = pack2h(h2, h3);
        *(uint32_t*)&Ql[r * PB + c]     = pack2h(l0, l1);
        *(uint32_t*)&Ql[r * PB + c + 2] = pack2h(l2, l3);
    }
    __syncthreads();

    // ---- Hoist Q fragments to registers (loop-invariant) ----
    uint32_t qfh[4][4], qfl[4][4];
#pragma unroll
    for (int u = 0; u < 4; u++) {
        const int w0 = u * 8 + t;
        qfh[u][0] = Qh32[(row16 + g) * PB32 + w0];
        qfh[u][1] = Qh32[(row16 + g + 8) * PB32 + w0];
        qfh[u][2] = Qh32[(row16 + g) * PB32 + w0 + 4];
        qfh[u][3] = Qh32[(row16 + g + 8) * PB32 + w0 + 4];
        qfl[u][0] = Ql32[(row16 + g) * PB32 + w0];
        qfl[u][1] = Ql32[(row16 + g + 8) * PB32 + w0];
        qfl[u][2] = Ql32[(row16 + g) * PB32 + w0 + 4];
        qfl[u][3] = Ql32[(row16 + g + 8) * PB32 + w0 + 4];
    }

    float oacc[8][4];
#pragma unroll
    for (int j = 0; j < 8; j++)
#pragma unroll
        for (int i = 0; i < 4; i++) oacc[j][i] = 0.f;
    float m0 = -1e30f, m1 = -1e30f, l0s = 0.f, l1s = 0.f;

    const int vrow = row16 + (lane & 15);
    const int vcg  = lane >> 4;

    for (int j0 = 0; j0 < TSEQ; j0 += 64) {
        cp_wait0();
        __syncthreads();   // staging ready; all warps past prev tile's mma

        // ---- Convert staging -> fp16 planes (K coalesced, V transposed) ----
#pragma unroll
        for (int it = 0; it < 8; it++) {
            int i = tid + it * 128;
            int r = i >> 4, c = (i & 15) * 4;
            float4 k4 = *(const float4*)&Ksg[r * PSG + c];
            *(uint32_t*)&Kh[r * PB + c]     = pack2h(__float2half_rn(k4.x), __float2half_rn(k4.y));
            *(uint32_t*)&Kh[r * PB + c + 2] = pack2h(__float2half_rn(k4.z), __float2half_rn(k4.w));
        }
#pragma unroll
        for (int it = 0; it < 8; it++) {
            int c = (vcg + 2 * it) * 4;
            float4 v4 = *(const float4*)&Vsg[vrow * PSG + c];
            Vh[(c + 0) * PB + vrow] = __float2half_rn(v4.x);
            Vh[(c + 1) * PB + vrow] = __float2half_rn(v4.y);
            Vh[(c + 2) * PB + vrow] = __float2half_rn(v4.z);
            Vh[(c + 3) * PB + vrow] = __float2half_rn(v4.w);
        }
        __syncthreads();   // planes ready; staging free for next tile

        // ---- Stage next tile (latency hidden behind mma/softmax below) ----
        if (j0 + 64 < TSEQ) {
#pragma unroll
            for (int it = 0; it < 8; it++) {
                int r = sgr + 8 * it;
                cp16(ksg_s + (uint32_t)(r * PSG + sgc) * 4,
                     Kb + (size_t)(j0 + 64 + r) * D_MODEL + sgc);
                cp16(vsg_s + (uint32_t)(r * PSG + sgc) * 4,
                     Vb + (size_t)(j0 + 64 + r) * D_MODEL + sgc);
            }
            cp_commit();
        }

        // ---- S = (Qh + Ql) Kh^T ----
        float sacc[8][4];
#pragma unroll
        for (int j = 0; j < 8; j++)
#pragma unroll
            for (int i = 0; i < 4; i++) sacc[j][i] = 0.f;

#pragma unroll
        for (int u = 0; u < 4; u++) {
            const int w0 = u * 8 + t;
#pragma unroll
            for (int j = 0; j < 8; j++) {
                uint32_t kh0 = Kh32[(j * 8 + g) * PB32 + w0];
                uint32_t kh1 = Kh32[(j * 8 + g) * PB32 + w0 + 4];
                mma_f16(sacc[j], qfh[u], kh0, kh1);
                mma_f16(sacc[j], qfl[u], kh0, kh1);
            }
        }

        // ---- Online softmax on fragments (rows g and g+8) ----
        float mx0 = -1e30f, mx1 = -1e30f;
#pragma unroll
        for (int j = 0; j < 8; j++) {
            mx0 = fmaxf(mx0, fmaxf(sacc[j][0], sacc[j][1]));
            mx1 = fmaxf(mx1, fmaxf(sacc[j][2], sacc[j][3]));
        }
        mx0 = fmaxf(mx0, __shfl_xor_sync(0xffffffffu, mx0, 1));
        mx0 = fmaxf(mx0, __shfl_xor_sync(0xffffffffu, mx0, 2));
        mx1 = fmaxf(mx1, __shfl_xor_sync(0xffffffffu, mx1, 1));
        mx1 = fmaxf(mx1, __shfl_xor_sync(0xffffffffu, mx1, 2));

        float mn0 = fmaxf(m0, mx0), mn1 = fmaxf(m1, mx1);
        float fac0 = __expf(m0 - mn0), fac1 = __expf(m1 - mn1);
        m0 = mn0; m1 = mn1;

        uint32_t ph01[8], ph23[8], pl01[8], pl23[8];
        float rs0 = 0.f, rs1 = 0.f;
#pragma unroll
        for (int j = 0; j < 8; j++) {
            float p0 = __expf(sacc[j][0] - mn0);
            float p1 = __expf(sacc[j][1] - mn0);
            float p2 = __expf(sacc[j][2] - mn1);
            float p3 = __expf(sacc[j][3] - mn1);
            rs0 += p0 + p1; rs1 += p2 + p3;
            __half h0, h1, h2, h3, q0, q1, q2, q3;
            hsplit(p0, h0, q0); hsplit(p1, h1, q1);
            hsplit(p2, h2, q2); hsplit(p3, h3, q3);
            ph01[j] = pack2h(h0, h1);
            ph23[j] = pack2h(h2, h3);
            pl01[j] = pack2h(q0, q1);
            pl23[j] = pack2h(q2, q3);
        }
        rs0 += __shfl_xor_sync(0xffffffffu, rs0, 1);
        rs0 += __shfl_xor_sync(0xffffffffu, rs0, 2);
        rs1 += __shfl_xor_sync(0xffffffffu, rs1, 1);
        rs1 += __shfl_xor_sync(0xffffffffu, rs1, 2);
        l0s = l0s * fac0 + rs0;
        l1s = l1s * fac1 + rs1;
#pragma unroll
        for (int j = 0; j < 8; j++) {
            oacc[j][0] *= fac0; oacc[j][1] *= fac0;
            oacc[j][2] *= fac1; oacc[j][3] *= fac1;
        }

        // ---- O += (Ph + Pl) Vh, P from registers ----
#pragma unroll
        for (int u = 0; u < 4; u++) {
            const int w0 = u * 8 + t;
            uint32_t pfh[4] = { ph01[2 * u], ph23[2 * u], ph01[2 * u + 1], ph23[2 * u + 1] };
            uint32_t pfl[4] = { pl01[2 * u], pl23[2 * u], pl01[2 * u + 1], pl23[2 * u + 1] };
#pragma unroll
            for (int j = 0; j < 8; j++) {
                uint32_t vh0 = Vh32[(j * 8 + g) * PB32 + w0];
                uint32_t vh1 = Vh32[(j * 8 + g) * PB32 + w0 + 4];
                mma_f16(oacc[j], pfh, vh0, vh1);
                mma_f16(oacc[j], pfl, vh0, vh1);
            }
        }
    }

    // ---- Epilogue: normalize, store ----
    float inv0 = 1.f / l0s, inv1 = 1.f / l1s;
    float* Ob = O + base + (size_t)qt * 64 * D_MODEL;
#pragma unroll
    for (int j = 0; j < 8; j++) {
        int col = j * 8 + 2 * t;
        *(float2*)(Ob + (size_t)(row16 + g) * D_MODEL + col) =
            make_float2(oacc[j][0] * inv0, oacc[j][1] * inv0);
        *(float2*)(Ob + (size_t)(row16 + g + 8) * D_MODEL + col) =
            make_float2(oacc[j][2] * inv1, oacc[j][3] * inv1);
    }
}

// ---------------------------------------------------------------------------
// Launch. Input order:
// 0:q 1:k 2:v 3:W_q 4:b_q 5:W_k 6:b_k 7:W_v 8:b_v 9:W_o 10:b_o
// ---------------------------------------------------------------------------
extern "C" void kernel_launch(void* const* d_in, const int* in_sizes, int n_in,
                              void* d_out, int out_size)
{
    (void)in_sizes; (void)n_in; (void)out_size;
    const float* q   = (const float*)d_in[0];
    const float* k   = (const float*)d_in[1];
    const float* v   = (const float*)d_in[2];
    const float* W_q = (const float*)d_in[3];
    const float* b_q = (const float*)d_in[4];
    const float* W_k = (const float*)d_in[5];
    const float* b_k = (const float*)d_in[6];
    const float* W_v = (const float*)d_in[7];
    const float* b_v = (const float*)d_in[8];
    const float* W_o = (const float*)d_in[9];
    const float* b_o = (const float*)d_in[10];
    float* out = (float*)d_out;

    float *gQ, *gK, *gV, *gA;
    cudaGetSymbolAddress((void**)&gQ, g_Q);
    cudaGetSymbolAddress((void**)&gK, g_K);
    cudaGetSymbolAddress((void**)&gV, g_V);
    cudaGetSymbolAddress((void**)&gA, g_A);

    // Fused Q/K/V projections: one launch, 1536 blocks, proven GEMM body.
    gemm_qkv_kernel<<<dim3(D_MODEL / BN, NTOK / BM, 3), 256>>>(
        q, k, v, W_q, W_k, W_v, b_q, b_k, b_v, gQ, gK, gV);

    cudaFuncSetAttribute(attention_f16_kernel,
                         cudaFuncAttributeMaxDynamicSharedMemorySize, ATT_SMEM);
    attention_f16_kernel<<<dim3(TSEQ / 64, HEADS, BATCH), 128, ATT_SMEM>>>(gQ, gK, gV, gA);

    gemm_o_kernel<<<dim3(D_MODEL / BN, NTOK / BM), 256>>>(gA, W_o, b_o, out);
}

// round 16
// speedup vs baseline: 1.5035x; 1.0431x over previous
#include <cuda_runtime.h>
#include <cuda_fp16.h>
#include <math.h>
#include <stdint.h>
#include <string.h>

#define D_MODEL 1024
#define NTOK    8192   // B*T
#define HEADS   16
#define HD      64
#define TSEQ    2048
#define BATCH   4

// GEMM tiling (tf32)
#define BM 128
#define BN 128
#define BKT 16
#define APAD 20
#define BPAD 136

// Attention smem pitches
#define PB   72    // fp16 plane pitch (elements); 36 words
#define PB32 36
#define PSG  68    // fp32 staging pitch (floats)

// Scratch (no allocation allowed — device globals). 16B-aligned.
__device__ __align__(16) float g_Q[NTOK * D_MODEL];
__device__ __align__(16) float g_K[NTOK * D_MODEL];
__device__ __align__(16) float g_V[NTOK * D_MODEL];
__device__ __align__(16) float g_A[NTOK * D_MODEL];

__device__ __forceinline__ float tf32r(float x) {
    uint32_t u;
    asm("cvt.rna.tf32.f32 %0, %1;" : "=r"(u) : "f"(x));
    return __uint_as_float(u);
}

__device__ __forceinline__ void mma_tf32(float* c, const uint32_t* a, const uint32_t* b) {
    asm volatile(
        "mma.sync.aligned.m16n8k8.row.col.f32.tf32.tf32.f32 "
        "{%0,%1,%2,%3}, {%4,%5,%6,%7}, {%8,%9}, {%0,%1,%2,%3};\n"
        : "+f"(c[0]), "+f"(c[1]), "+f"(c[2]), "+f"(c[3])
        : "r"(a[0]), "r"(a[1]), "r"(a[2]), "r"(a[3]), "r"(b[0]), "r"(b[1]));
}

__device__ __forceinline__ void mma_f16(float* c, const uint32_t* a, uint32_t b0, uint32_t b1) {
    asm volatile(
        "mma.sync.aligned.m16n8k16.row.col.f32.f16.f16.f32 "
        "{%0,%1,%2,%3}, {%4,%5,%6,%7}, {%8,%9}, {%0,%1,%2,%3};\n"
        : "+f"(c[0]), "+f"(c[1]), "+f"(c[2]), "+f"(c[3])
        : "r"(a[0]), "r"(a[1]), "r"(a[2]), "r"(a[3]), "r"(b0), "r"(b1));
}

// split fp32 -> fp16 hi + fp16 lo (hi+lo reproduces ~22 mantissa bits)
__device__ __forceinline__ void hsplit(float x, __half& h, __half& l) {
    h = __float2half_rn(x);
    l = __float2half_rn(x - __half2float(h));
}

// pack two fp16 into one 32-bit word (lo -> low half)
__device__ __forceinline__ uint32_t pack2h(__half lo, __half hi) {
    __half2 p = __halves2half2(lo, hi);
    uint32_t u;
    memcpy(&u, &p, 4);
    return u;
}

__device__ __forceinline__ uint32_t cvta_smem(const void* p) {
    return (uint32_t)__cvta_generic_to_shared(p);
}

// cp.async 16B (cg: L2-only, streaming)
__device__ __forceinline__ void cp16(uint32_t dst, const void* src) {
    asm volatile("cp.async.cg.shared.global [%0], [%1], 16;" :: "r"(dst), "l"(src));
}
__device__ __forceinline__ void cp_commit() {
    asm volatile("cp.async.commit_group;" ::: "memory");
}
__device__ __forceinline__ void cp_wait0() {
    asm volatile("cp.async.wait_group 0;" ::: "memory");
}

// ---------------------------------------------------------------------------
// TF32 tensor-core GEMM, cp.async ping-pong staging (fp32 in smem, cvt at
// fragment load). One __syncthreads per K-step; no STS; no register prefetch.
// ---------------------------------------------------------------------------
__device__ __forceinline__
void gemm_tf32_cp_body(const float* __restrict__ A, const float* __restrict__ B,
                       const float* __restrict__ bias, float* __restrict__ C,
                       int M, int N, int K)
{
    __shared__ float As[2][BM * APAD];
    __shared__ float Bs[2][BKT * BPAD];

    const int tid  = threadIdx.x;
    const int warp = tid >> 5, lane = tid & 31;
    const int g = lane >> 2, t = lane & 3;
    const int wm = (warp >> 2) * 64;
    const int wn = (warp & 3) * 32;

    const int bx = blockIdx.x, by = blockIdx.y;
    const float* Ab = A + (size_t)by * BM * K;
    const float* Bb = B + bx * BN;

    // staging assignment: A 128x16 (2 cp16/thread), B 16x128 (2 cp16/thread)
    const int arow = tid >> 1, acol = (tid & 1) * 8;
    const int brow = tid >> 4, bcol = (tid & 15) * 8;

    const uint32_t as_s[2] = { cvta_smem(As[0]), cvta_smem(As[1]) };
    const uint32_t bs_s[2] = { cvta_smem(Bs[0]), cvta_smem(Bs[1]) };
    const uint32_t a_off = (uint32_t)(arow * APAD + acol) * 4;
    const uint32_t b_off = (uint32_t)(brow * BPAD + bcol) * 4;

    // stage 0
    {
        cp16(as_s[0] + a_off,      Ab + (size_t)arow * K + acol);
        cp16(as_s[0] + a_off + 16, Ab + (size_t)arow * K + acol + 4);
        cp16(bs_s[0] + b_off,      Bb + (size_t)brow * N + bcol);
        cp16(bs_s[0] + b_off + 16, Bb + (size_t)brow * N + bcol + 4);
        cp_commit();
    }

    float acc[4][4][4];
#pragma unroll
    for (int mt = 0; mt < 4; mt++)
#pragma unroll
        for (int nt = 0; nt < 4; nt++)
#pragma unroll
            for (int i = 0; i < 4; i++) acc[mt][nt][i] = 0.f;

    int buf = 0;
    for (int k0 = 0; k0 < K; k0 += BKT) {
        cp_wait0();
        __syncthreads();   // staged tile visible to all; prev reads of buf^1 done

        if (k0 + BKT < K) {
            const int nb = buf ^ 1;
            cp16(as_s[nb] + a_off,      Ab + (size_t)arow * K + k0 + BKT + acol);
            cp16(as_s[nb] + a_off + 16, Ab + (size_t)arow * K + k0 + BKT + acol + 4);
            cp16(bs_s[nb] + b_off,      Bb + (size_t)(k0 + BKT + brow) * N + bcol);
            cp16(bs_s[nb] + b_off + 16, Bb + (size_t)(k0 + BKT + brow) * N + bcol + 4);
            cp_commit();
        }

        const float* Asb = As[buf];
        const float* Bsb = Bs[buf];
#pragma unroll
        for (int kk = 0; kk < BKT; kk += 8) {
            uint32_t af[4][4];
#pragma unroll
            for (int mt = 0; mt < 4; mt++) {
                const float* ap = Asb + (wm + mt * 16 + g) * APAD + kk + t;
                af[mt][0] = __float_as_uint(tf32r(ap[0]));
                af[mt][1] = __float_as_uint(tf32r(ap[8 * APAD]));
                af[mt][2] = __float_as_uint(tf32r(ap[4]));
                af[mt][3] = __float_as_uint(tf32r(ap[8 * APAD + 4]));
            }
            uint32_t bf[4][2];
#pragma unroll
            for (int nt = 0; nt < 4; nt++) {
                const float* bp = Bsb + (kk + t) * BPAD + wn + nt * 8 + g;
                bf[nt][0] = __float_as_uint(tf32r(bp[0]));
                bf[nt][1] = __float_as_uint(tf32r(bp[4 * BPAD]));
            }
#pragma unroll
            for (int mt = 0; mt < 4; mt++)
#pragma unroll
                for (int nt = 0; nt < 4; nt++)
                    mma_tf32(acc[mt][nt], af[mt], bf[nt]);
        }
        buf ^= 1;
    }

#pragma unroll
    for (int mt = 0; mt < 4; mt++) {
        int row0 = by * BM + wm + mt * 16 + g;
#pragma unroll
        for (int nt = 0; nt < 4; nt++) {
            int col = bx * BN + wn + nt * 8 + 2 * t;
            float b0 = bias[col], b1 = bias[col + 1];
            float2 r0 = make_float2(acc[mt][nt][0] + b0, acc[mt][nt][1] + b1);
            float2 r1 = make_float2(acc[mt][nt][2] + b0, acc[mt][nt][3] + b1);
            *(float2*)(C + (size_t)row0 * N + col) = r0;
            *(float2*)(C + (size_t)(row0 + 8) * N + col) = r1;
        }
    }
}

// Fused Q/K/V projections: blockIdx.z selects input/weight/bias/output.
__global__ __launch_bounds__(256, 2)
void gemm_qkv_kernel(const float* __restrict__ q, const float* __restrict__ k,
                     const float* __restrict__ v,
                     const float* __restrict__ Wq, const float* __restrict__ Wk,
                     const float* __restrict__ Wv,
                     const float* __restrict__ bq, const float* __restrict__ bk,
                     const float* __restrict__ bv,
                     float* __restrict__ Cq, float* __restrict__ Ck,
                     float* __restrict__ Cv)
{
    const int z = blockIdx.z;
    const float* A = (z == 0) ? q : (z == 1) ? k : v;
    const float* B = (z == 0) ? Wq : (z == 1) ? Wk : Wv;
    const float* bias = (z == 0) ? bq : (z == 1) ? bk : bv;
    float* C = (z == 0) ? Cq : (z == 1) ? Ck : Cv;
    gemm_tf32_cp_body(A, B, bias, C, NTOK, D_MODEL, D_MODEL);
}

__global__ __launch_bounds__(256, 2)
void gemm_o_kernel(const float* __restrict__ A, const float* __restrict__ B,
                   const float* __restrict__ bias, float* __restrict__ C)
{
    gemm_tf32_cp_body(A, B, bias, C, NTOK, D_MODEL, D_MODEL);
}

// ---------------------------------------------------------------------------
// Flash attention, fp16 A-side-split MMA + cp.async K/V staging pipeline.
// Exact R13-proven version (bit-identical numerics).
// ---------------------------------------------------------------------------
#define ATT_SMEM 71680

__global__ __launch_bounds__(128, 3)
void attention_f16_kernel(const float* __restrict__ Q, const float* __restrict__ K,
                          const float* __restrict__ V, float* __restrict__ O)
{
    extern __shared__ __align__(16) char smraw[];
    __half* Qh = (__half*)(smraw);
    __half* Ql = (__half*)(smraw + 9216);
    __half* Kh = (__half*)(smraw + 18432);
    __half* Vh = (__half*)(smraw + 27648);
    float*  Ksg = (float*)(smraw + 36864);
    float*  Vsg = (float*)(smraw + 54272);

    const uint32_t* Qh32 = (const uint32_t*)Qh;
    const uint32_t* Ql32 = (const uint32_t*)Ql;
    const uint32_t* Kh32 = (const uint32_t*)Kh;
    const uint32_t* Vh32 = (const uint32_t*)Vh;

    const uint32_t ksg_s = cvta_smem(Ksg);
    const uint32_t vsg_s = cvta_smem(Vsg);

    const int tid  = threadIdx.x;
    const int warp = tid >> 5, lane = tid & 31;
    const int g = lane >> 2, t = lane & 3;
    const int row16 = warp * 16;

    const int qt = blockIdx.x, h = blockIdx.y, b = blockIdx.z;
    const size_t base = ((size_t)b * TSEQ) * D_MODEL + (size_t)h * HD;
    const float* Qb = Q + base + (size_t)qt * 64 * D_MODEL;
    const float* Kb = K + base;
    const float* Vb = V + base;

    const int sgc = (tid & 15) * 4;
    const int sgr = tid >> 4;

    // ---- Stage tile 0 K/V ----
#pragma unroll
    for (int it = 0; it < 8; it++) {
        int r = sgr + 8 * it;
        cp16(ksg_s + (uint32_t)(r * PSG + sgc) * 4, Kb + (size_t)r * D_MODEL + sgc);
        cp16(vsg_s + (uint32_t)(r * PSG + sgc) * 4, Vb + (size_t)r * D_MODEL + sgc);
    }
    cp_commit();

    // ---- Load + scale + split Q once (64x64) ----
#pragma unroll
    for (int it = 0; it < 8; it++) {
        int i = tid + it * 128;
        int r = i >> 4, c = (i & 15) * 4;
        float4 q4 = *(const float4*)(Qb + (size_t)r * D_MODEL + c);
        __half h0, h1, h2, h3, l0, l1, l2, l3;
        hsplit(q4.x * 0.125f, h0, l0); hsplit(q4.y * 0.125f, h1, l1);
        hsplit(q4.z * 0.125f, h2, l2); hsplit(q4.w * 0.125f, h3, l3);
        *(uint32_t*)&Qh[r * PB + c]     = pack2h(h0, h1);
        *(uint32_t*)&Qh[r * PB + c + 2] = pack2h(h2, h3);
        *(uint32_t*)&Ql[r * PB + c]     = pack2h(l0, l1);
        *(uint32_t*)&Ql[r * PB + c + 2] = pack2h(l2, l3);
    }
    __syncthreads();

    // ---- Hoist Q fragments to registers ----
    uint32_t qfh[4][4], qfl[4][4];
#pragma unroll
    for (int u = 0; u < 4; u++) {
        const int w0 = u * 8 + t;
        qfh[u][0] = Qh32[(row16 + g) * PB32 + w0];
        qfh[u][1] = Qh32[(row16 + g + 8) * PB32 + w0];
        qfh[u][2] = Qh32[(row16 + g) * PB32 + w0 + 4];
        qfh[u][3] = Qh32[(row16 + g + 8) * PB32 + w0 + 4];
        qfl[u][0] = Ql32[(row16 + g) * PB32 + w0];
        qfl[u][1] = Ql32[(row16 + g + 8) * PB32 + w0];
        qfl[u][2] = Ql32[(row16 + g) * PB32 + w0 + 4];
        qfl[u][3] = Ql32[(row16 + g + 8) * PB32 + w0 + 4];
    }

    float oacc[8][4];
#pragma unroll
    for (int j = 0; j < 8; j++)
#pragma unroll
        for (int i = 0; i < 4; i++) oacc[j][i] = 0.f;
    float m0 = -1e30f, m1 = -1e30f, l0s = 0.f, l1s = 0.f;

    const int vrow = row16 + (lane & 15);
    const int vcg  = lane >> 4;

    for (int j0 = 0; j0 < TSEQ; j0 += 64) {
        cp_wait0();
        __syncthreads();

        // ---- Convert staging -> fp16 planes ----
#pragma unroll
        for (int it = 0; it < 8; it++) {
            int i = tid + it * 128;
            int r = i >> 4, c = (i & 15) * 4;
            float4 k4 = *(const float4*)&Ksg[r * PSG + c];
            *(uint32_t*)&Kh[r * PB + c]     = pack2h(__float2half_rn(k4.x), __float2half_rn(k4.y));
            *(uint32_t*)&Kh[r * PB + c + 2] = pack2h(__float2half_rn(k4.z), __float2half_rn(k4.w));
        }
#pragma unroll
        for (int it = 0; it < 8; it++) {
            int c = (vcg + 2 * it) * 4;
            float4 v4 = *(const float4*)&Vsg[vrow * PSG + c];
            Vh[(c + 0) * PB + vrow] = __float2half_rn(v4.x);
            Vh[(c + 1) * PB + vrow] = __float2half_rn(v4.y);
            Vh[(c + 2) * PB + vrow] = __float2half_rn(v4.z);
            Vh[(c + 3) * PB + vrow] = __float2half_rn(v4.w);
        }
        __syncthreads();

        // ---- Stage next tile ----
        if (j0 + 64 < TSEQ) {
#pragma unroll
            for (int it = 0; it < 8; it++) {
                int r = sgr + 8 * it;
                cp16(ksg_s + (uint32_t)(r * PSG + sgc) * 4,
                     Kb + (size_t)(j0 + 64 + r) * D_MODEL + sgc);
                cp16(vsg_s + (uint32_t)(r * PSG + sgc) * 4,
                     Vb + (size_t)(j0 + 64 + r) * D_MODEL + sgc);
            }
            cp_commit();
        }

        // ---- S = (Qh + Ql) Kh^T ----
        float sacc[8][4];
#pragma unroll
        for (int j = 0; j < 8; j++)
#pragma unroll
            for (int i = 0; i < 4; i++) sacc[j][i] = 0.f;

#pragma unroll
        for (int u = 0; u < 4; u++) {
            const int w0 = u * 8 + t;
#pragma unroll
            for (int j = 0; j < 8; j++) {
                uint32_t kh0 = Kh32[(j * 8 + g) * PB32 + w0];
                uint32_t kh1 = Kh32[(j * 8 + g) * PB32 + w0 + 4];
                mma_f16(sacc[j], qfh[u], kh0, kh1);
                mma_f16(sacc[j], qfl[u], kh0, kh1);
            }
        }

        // ---- Online softmax ----
        float mx0 = -1e30f, mx1 = -1e30f;
#pragma unroll
        for (int j = 0; j < 8; j++) {
            mx0 = fmaxf(mx0, fmaxf(sacc[j][0], sacc[j][1]));
            mx1 = fmaxf(mx1, fmaxf(sacc[j][2], sacc[j][3]));
        }
        mx0 = fmaxf(mx0, __shfl_xor_sync(0xffffffffu, mx0, 1));
        mx0 = fmaxf(mx0, __shfl_xor_sync(0xffffffffu, mx0, 2));
        mx1 = fmaxf(mx1, __shfl_xor_sync(0xffffffffu, mx1, 1));
        mx1 = fmaxf(mx1, __shfl_xor_sync(0xffffffffu, mx1, 2));

        float mn0 = fmaxf(m0, mx0), mn1 = fmaxf(m1, mx1);
        float fac0 = __expf(m0 - mn0), fac1 = __expf(m1 - mn1);
        m0 = mn0; m1 = mn1;

        uint32_t ph01[8], ph23[8], pl01[8], pl23[8];
        float rs0 = 0.f, rs1 = 0.f;
#pragma unroll
        for (int j = 0; j < 8; j++) {
            float p0 = __expf(sacc[j][0] - mn0);
            float p1 = __expf(sacc[j][1] - mn0);
            float p2 = __expf(sacc[j][2] - mn1);
            float p3 = __expf(sacc[j][3] - mn1);
            rs0 += p0 + p1; rs1 += p2 + p3;
            __half h0, h1, h2, h3, q0, q1, q2, q3;
            hsplit(p0, h0, q0); hsplit(p1, h1, q1);
            hsplit(p2, h2, q2); hsplit(p3, h3, q3);
            ph01[j] = pack2h(h0, h1);
            ph23[j] = pack2h(h2, h3);
            pl01[j] = pack2h(q0, q1);
            pl23[j] = pack2h(q2, q3);
        }
        rs0 += __shfl_xor_sync(0xffffffffu, rs0, 1);
        rs0 += __shfl_xor_sync(0xffffffffu, rs0, 2);
        rs1 += __shfl_xor_sync(0xffffffffu, rs1, 1);
        rs1 += __shfl_xor_sync(0xffffffffu, rs1, 2);
        l0s = l0s * fac0 + rs0;
        l1s = l1s * fac1 + rs1;
#pragma unroll
        for (int j = 0; j < 8; j++) {
            oacc[j][0] *= fac0; oacc[j][1] *= fac0;
            oacc[j][2] *= fac1; oacc[j][3] *= fac1;
        }

        // ---- O += (Ph + Pl) Vh ----
#pragma unroll
        for (int u = 0; u < 4; u++) {
            const int w0 = u * 8 + t;
            uint32_t pfh[4] = { ph01[2 * u], ph23[2 * u], ph01[2 * u + 1], ph23[2 * u + 1] };
            uint32_t pfl[4] = { pl01[2 * u], pl23[2 * u], pl01[2 * u + 1], pl23[2 * u + 1] };
#pragma unroll
            for (int j = 0; j < 8; j++) {
                uint32_t vh0 = Vh32[(j * 8 + g) * PB32 + w0];
                uint32_t vh1 = Vh32[(j * 8 + g) * PB32 + w0 + 4];
                mma_f16(oacc[j], pfh, vh0, vh1);
                mma_f16(oacc[j], pfl, vh0, vh1);
            }
        }
    }

    // ---- Epilogue ----
    float inv0 = 1.f / l0s, inv1 = 1.f / l1s;
    float* Ob = O + base + (size_t)qt * 64 * D_MODEL;
#pragma unroll
    for (int j = 0; j < 8; j++) {
        int col = j * 8 + 2 * t;
        *(float2*)(Ob + (size_t)(row16 + g) * D_MODEL + col) =
            make_float2(oacc[j][0] * inv0, oacc[j][1] * inv0);
        *(float2*)(Ob + (size_t)(row16 + g + 8) * D_MODEL + col) =
            make_float2(oacc[j][2] * inv1, oacc[j][3] * inv1);
    }
}

// ---------------------------------------------------------------------------
// Launch. Input order:
// 0:q 1:k 2:v 3:W_q 4:b_q 5:W_k 6:b_k 7:W_v 8:b_v 9:W_o 10:b_o
// ---------------------------------------------------------------------------
extern "C" void kernel_launch(void* const* d_in, const int* in_sizes, int n_in,
                              void* d_out, int out_size)
{
    (void)in_sizes; (void)n_in; (void)out_size;
    const float* q   = (const float*)d_in[0];
    const float* k   = (const float*)d_in[1];
    const float* v   = (const float*)d_in[2];
    const float* W_q = (const float*)d_in[3];
    const float* b_q = (const float*)d_in[4];
    const float* W_k = (const float*)d_in[5];
    const float* b_k = (const float*)d_in[6];
    const float* W_v = (const float*)d_in[7];
    const float* b_v = (const float*)d_in[8];
    const float* W_o = (const float*)d_in[9];
    const float* b_o = (const float*)d_in[10];
    float* out = (float*)d_out;

    float *gQ, *gK, *gV, *gA;
    cudaGetSymbolAddress((void**)&gQ, g_Q);
    cudaGetSymbolAddress((void**)&gK, g_K);
    cudaGetSymbolAddress((void**)&gV, g_V);
    cudaGetSymbolAddress((void**)&gA, g_A);

    gemm_qkv_kernel<<<dim3(D_MODEL / BN, NTOK / BM, 3), 256>>>(
        q, k, v, W_q, W_k, W_v, b_q, b_k, b_v, gQ, gK, gV);

    cudaFuncSetAttribute(attention_f16_kernel,
                         cudaFuncAttributeMaxDynamicSharedMemorySize, ATT_SMEM);
    attention_f16_kernel<<<dim3(TSEQ / 64, HEADS, BATCH), 128, ATT_SMEM>>>(gQ, gK, gV, gA);

    gemm_o_kernel<<<dim3(D_MODEL / BN, NTOK / BM), 256>>>(gA, W_o, b_o, out);
}

// round 17
// speedup vs baseline: 1.5879x; 1.0561x over previous
#include <cuda_runtime.h>
#include <cuda_fp16.h>
#include <math.h>
#include <stdint.h>
#include <string.h>

#define D_MODEL 1024
#define NTOK    8192   // B*T
#define HEADS   16
#define HD      64
#define TSEQ    2048
#define BATCH   4

// GEMM tiling (tf32)
#define BM 128
#define BN 128
#define BKT 16
#define APAD 20
#define BPAD 136
#define NSTAGE 3

// Attention smem pitches
#define PB   72    // fp16 plane pitch (elements); 36 words
#define PB32 36
#define PSG  68    // fp32 staging pitch (floats)

// Scratch (no allocation allowed — device globals). 16B-aligned.
__device__ __align__(16) float g_Q[NTOK * D_MODEL];
__device__ __align__(16) float g_K[NTOK * D_MODEL];
__device__ __align__(16) float g_V[NTOK * D_MODEL];
__device__ __align__(16) float g_A[NTOK * D_MODEL];

__device__ __forceinline__ float tf32r(float x) {
    uint32_t u;
    asm("cvt.rna.tf32.f32 %0, %1;" : "=r"(u) : "f"(x));
    return __uint_as_float(u);
}

__device__ __forceinline__ void mma_tf32(float* c, const uint32_t* a, const uint32_t* b) {
    asm volatile(
        "mma.sync.aligned.m16n8k8.row.col.f32.tf32.tf32.f32 "
        "{%0,%1,%2,%3}, {%4,%5,%6,%7}, {%8,%9}, {%0,%1,%2,%3};\n"
        : "+f"(c[0]), "+f"(c[1]), "+f"(c[2]), "+f"(c[3])
        : "r"(a[0]), "r"(a[1]), "r"(a[2]), "r"(a[3]), "r"(b[0]), "r"(b[1]));
}

__device__ __forceinline__ void mma_f16(float* c, const uint32_t* a, uint32_t b0, uint32_t b1) {
    asm volatile(
        "mma.sync.aligned.m16n8k16.row.col.f32.f16.f16.f32 "
        "{%0,%1,%2,%3}, {%4,%5,%6,%7}, {%8,%9}, {%0,%1,%2,%3};\n"
        : "+f"(c[0]), "+f"(c[1]), "+f"(c[2]), "+f"(c[3])
        : "r"(a[0]), "r"(a[1]), "r"(a[2]), "r"(a[3]), "r"(b0), "r"(b1));
}

// split fp32 -> fp16 hi + fp16 lo (hi+lo reproduces ~22 mantissa bits)
__device__ __forceinline__ void hsplit(float x, __half& h, __half& l) {
    h = __float2half_rn(x);
    l = __float2half_rn(x - __half2float(h));
}

// pack two fp16 into one 32-bit word (lo -> low half)
__device__ __forceinline__ uint32_t pack2h(__half lo, __half hi) {
    __half2 p = __halves2half2(lo, hi);
    uint32_t u;
    memcpy(&u, &p, 4);
    return u;
}

__device__ __forceinline__ uint32_t cvta_smem(const void* p) {
    return (uint32_t)__cvta_generic_to_shared(p);
}

// cp.async 16B (cg: L2-only, streaming)
__device__ __forceinline__ void cp16(uint32_t dst, const void* src) {
    asm volatile("cp.async.cg.shared.global [%0], [%1], 16;" :: "r"(dst), "l"(src));
}
__device__ __forceinline__ void cp_commit() {
    asm volatile("cp.async.commit_group;" ::: "memory");
}
__device__ __forceinline__ void cp_wait0() {
    asm volatile("cp.async.wait_group 0;" ::: "memory");
}
__device__ __forceinline__ void cp_wait1() {
    asm volatile("cp.async.wait_group 1;" ::: "memory");
}

// ---------------------------------------------------------------------------
// TF32 tensor-core GEMM, 3-stage cp.async ring (fp32 in smem, cvt at fragment
// load). wait_group 1 keeps one load-group in flight across ~2 compute phases.
// ---------------------------------------------------------------------------
__device__ __forceinline__
void gemm_tf32_cp_body(const float* __restrict__ A, const float* __restrict__ B,
                       const float* __restrict__ bias, float* __restrict__ C,
                       int M, int N, int K)
{
    __shared__ float As[NSTAGE][BM * APAD];
    __shared__ float Bs[NSTAGE][BKT * BPAD];

    const int tid  = threadIdx.x;
    const int warp = tid >> 5, lane = tid & 31;
    const int g = lane >> 2, t = lane & 3;
    const int wm = (warp >> 2) * 64;
    const int wn = (warp & 3) * 32;

    const int bx = blockIdx.x, by = blockIdx.y;
    const float* Ab = A + (size_t)by * BM * K;
    const float* Bb = B + bx * BN;

    const int arow = tid >> 1, acol = (tid & 1) * 8;
    const int brow = tid >> 4, bcol = (tid & 15) * 8;

    uint32_t as_s[NSTAGE], bs_s[NSTAGE];
#pragma unroll
    for (int s = 0; s < NSTAGE; s++) {
        as_s[s] = cvta_smem(As[s]);
        bs_s[s] = cvta_smem(Bs[s]);
    }
    const uint32_t a_off = (uint32_t)(arow * APAD + acol) * 4;
    const uint32_t b_off = (uint32_t)(brow * BPAD + bcol) * 4;

    const int NSTEP = K / BKT;

    // prologue: stage 0 and 1
#pragma unroll
    for (int s = 0; s < 2; s++) {
        cp16(as_s[s] + a_off,      Ab + (size_t)arow * K + s * BKT + acol);
        cp16(as_s[s] + a_off + 16, Ab + (size_t)arow * K + s * BKT + acol + 4);
        cp16(bs_s[s] + b_off,      Bb + (size_t)(s * BKT + brow) * N + bcol);
        cp16(bs_s[s] + b_off + 16, Bb + (size_t)(s * BKT + brow) * N + bcol + 4);
        cp_commit();
    }

    float acc[4][4][4];
#pragma unroll
    for (int mt = 0; mt < 4; mt++)
#pragma unroll
        for (int nt = 0; nt < 4; nt++)
#pragma unroll
            for (int i = 0; i < 4; i++) acc[mt][nt][i] = 0.f;

    for (int s = 0; s < NSTEP; s++) {
        const bool more = (s + 2) < NSTEP;
        if (more) cp_wait1(); else cp_wait0();   // stage s resident
        __syncthreads();                          // prev reads of reused buf done

        if (more) {
            const int nb = (s + 2) % NSTAGE;
            const int k0 = (s + 2) * BKT;
            cp16(as_s[nb] + a_off,      Ab + (size_t)arow * K + k0 + acol);
            cp16(as_s[nb] + a_off + 16, Ab + (size_t)arow * K + k0 + acol + 4);
            cp16(bs_s[nb] + b_off,      Bb + (size_t)(k0 + brow) * N + bcol);
            cp16(bs_s[nb] + b_off + 16, Bb + (size_t)(k0 + brow) * N + bcol + 4);
            cp_commit();
        }

        const float* Asb = As[s % NSTAGE];
        const float* Bsb = Bs[s % NSTAGE];
#pragma unroll
        for (int kk = 0; kk < BKT; kk += 8) {
            uint32_t af[4][4];
#pragma unroll
            for (int mt = 0; mt < 4; mt++) {
                const float* ap = Asb + (wm + mt * 16 + g) * APAD + kk + t;
                af[mt][0] = __float_as_uint(tf32r(ap[0]));
                af[mt][1] = __float_as_uint(tf32r(ap[8 * APAD]));
                af[mt][2] = __float_as_uint(tf32r(ap[4]));
                af[mt][3] = __float_as_uint(tf32r(ap[8 * APAD + 4]));
            }
            uint32_t bf[4][2];
#pragma unroll
            for (int nt = 0; nt < 4; nt++) {
                const float* bp = Bsb + (kk + t) * BPAD + wn + nt * 8 + g;
                bf[nt][0] = __float_as_uint(tf32r(bp[0]));
                bf[nt][1] = __float_as_uint(tf32r(bp[4 * BPAD]));
            }
#pragma unroll
            for (int mt = 0; mt < 4; mt++)
#pragma unroll
                for (int nt = 0; nt < 4; nt++)
                    mma_tf32(acc[mt][nt], af[mt], bf[nt]);
        }
    }

#pragma unroll
    for (int mt = 0; mt < 4; mt++) {
        int row0 = by * BM + wm + mt * 16 + g;
#pragma unroll
        for (int nt = 0; nt < 4; nt++) {
            int col = bx * BN + wn + nt * 8 + 2 * t;
            float b0 = bias[col], b1 = bias[col + 1];
            float2 r0 = make_float2(acc[mt][nt][0] + b0, acc[mt][nt][1] + b1);
            float2 r1 = make_float2(acc[mt][nt][2] + b0, acc[mt][nt][3] + b1);
            *(float2*)(C + (size_t)row0 * N + col) = r0;
            *(float2*)(C + (size_t)(row0 + 8) * N + col) = r1;
        }
    }
}

// Fused Q/K/V projections: blockIdx.z selects input/weight/bias/output.
__global__ __launch_bounds__(256, 2)
void gemm_qkv_kernel(const float* __restrict__ q, const float* __restrict__ k,
                     const float* __restrict__ v,
                     const float* __restrict__ Wq, const float* __restrict__ Wk,
                     const float* __restrict__ Wv,
                     const float* __restrict__ bq, const float* __restrict__ bk,
                     const float* __restrict__ bv,
                     float* __restrict__ Cq, float* __restrict__ Ck,
                     float* __restrict__ Cv)
{
    const int z = blockIdx.z;
    const float* A = (z == 0) ? q : (z == 1) ? k : v;
    const float* B = (z == 0) ? Wq : (z == 1) ? Wk : Wv;
    const float* bias = (z == 0) ? bq : (z == 1) ? bk : bv;
    float* C = (z == 0) ? Cq : (z == 1) ? Ck : Cv;
    gemm_tf32_cp_body(A, B, bias, C, NTOK, D_MODEL, D_MODEL);
}

__global__ __launch_bounds__(256, 2)
void gemm_o_kernel(const float* __restrict__ A, const float* __restrict__ B,
                   const float* __restrict__ bias, float* __restrict__ C)
{
    gemm_tf32_cp_body(A, B, bias, C, NTOK, D_MODEL, D_MODEL);
}

// ---------------------------------------------------------------------------
// Flash attention, fp16 A-side-split MMA + cp.async K/V staging pipeline.
// Exact R13-proven version (bit-identical numerics).
// ---------------------------------------------------------------------------
#define ATT_SMEM 71680

__global__ __launch_bounds__(128, 3)
void attention_f16_kernel(const float* __restrict__ Q, const float* __restrict__ K,
                          const float* __restrict__ V, float* __restrict__ O)
{
    extern __shared__ __align__(16) char smraw[];
    __half* Qh = (__half*)(smraw);
    __half* Ql = (__half*)(smraw + 9216);
    __half* Kh = (__half*)(smraw + 18432);
    __half* Vh = (__half*)(smraw + 27648);
    float*  Ksg = (float*)(smraw + 36864);
    float*  Vsg = (float*)(smraw + 54272);

    const uint32_t* Qh32 = (const uint32_t*)Qh;
    const uint32_t* Ql32 = (const uint32_t*)Ql;
    const uint32_t* Kh32 = (const uint32_t*)Kh;
    const uint32_t* Vh32 = (const uint32_t*)Vh;

    const uint32_t ksg_s = cvta_smem(Ksg);
    const uint32_t vsg_s = cvta_smem(Vsg);

    const int tid  = threadIdx.x;
    const int warp = tid >> 5, lane = tid & 31;
    const int g = lane >> 2, t = lane & 3;
    const int row16 = warp * 16;

    const int qt = blockIdx.x, h = blockIdx.y, b = blockIdx.z;
    const size_t base = ((size_t)b * TSEQ) * D_MODEL + (size_t)h * HD;
    const float* Qb = Q + base + (size_t)qt * 64 * D_MODEL;
    const float* Kb = K + base;
    const float* Vb = V + base;

    const int sgc = (tid & 15) * 4;
    const int sgr = tid >> 4;

    // ---- Stage tile 0 K/V ----
#pragma unroll
    for (int it = 0; it < 8; it++) {
        int r = sgr + 8 * it;
        cp16(ksg_s + (uint32_t)(r * PSG + sgc) * 4, Kb + (size_t)r * D_MODEL + sgc);
        cp16(vsg_s + (uint32_t)(r * PSG + sgc) * 4, Vb + (size_t)r * D_MODEL + sgc);
    }
    cp_commit();

    // ---- Load + scale + split Q once (64x64) ----
#pragma unroll
    for (int it = 0; it < 8; it++) {
        int i = tid + it * 128;
        int r = i >> 4, c = (i & 15) * 4;
        float4 q4 = *(const float4*)(Qb + (size_t)r * D_MODEL + c);
        __half h0, h1, h2, h3, l0, l1, l2, l3;
        hsplit(q4.x * 0.125f, h0, l0); hsplit(q4.y * 0.125f, h1, l1);
        hsplit(q4.z * 0.125f, h2, l2); hsplit(q4.w * 0.125f, h3, l3);
        *(uint32_t*)&Qh[r * PB + c]     = pack2h(h0, h1);
        *(uint32_t*)&Qh[r * PB + c + 2] = pack2h(h2, h3);
        *(uint32_t*)&Ql[r * PB + c]     = pack2h(l0, l1);
        *(uint32_t*)&Ql[r * PB + c + 2] = pack2h(l2, l3);
    }
    __syncthreads();

    // ---- Hoist Q fragments to registers ----
    uint32_t qfh[4][4], qfl[4][4];
#pragma unroll
    for (int u = 0; u < 4; u++) {
        const int w0 = u * 8 + t;
        qfh[u][0] = Qh32[(row16 + g) * PB32 + w0];
        qfh[u][1] = Qh32[(row16 + g + 8) * PB32 + w0];
        qfh[u][2] = Qh32[(row16 + g) * PB32 + w0 + 4];
        qfh[u][3] = Qh32[(row16 + g + 8) * PB32 + w0 + 4];
        qfl[u][0] = Ql32[(row16 + g) * PB32 + w0];
        qfl[u][1] = Ql32[(row16 + g + 8) * PB32 + w0];
        qfl[u][2] = Ql32[(row16 + g) * PB32 + w0 + 4];
        qfl[u][3] = Ql32[(row16 + g + 8) * PB32 + w0 + 4];
    }

    float oacc[8][4];
#pragma unroll
    for (int j = 0; j < 8; j++)
#pragma unroll
        for (int i = 0; i < 4; i++) oacc[j][i] = 0.f;
    float m0 = -1e30f, m1 = -1e30f, l0s = 0.f, l1s = 0.f;

    const int vrow = row16 + (lane & 15);
    const int vcg  = lane >> 4;

    for (int j0 = 0; j0 < TSEQ; j0 += 64) {
        cp_wait0();
        __syncthreads();

        // ---- Convert staging -> fp16 planes ----
#pragma unroll
        for (int it = 0; it < 8; it++) {
            int i = tid + it * 128;
            int r = i >> 4, c = (i & 15) * 4;
            float4 k4 = *(const float4*)&Ksg[r * PSG + c];
            *(uint32_t*)&Kh[r * PB + c]     = pack2h(__float2half_rn(k4.x), __float2half_rn(k4.y));
            *(uint32_t*)&Kh[r * PB + c + 2] = pack2h(__float2half_rn(k4.z), __float2half_rn(k4.w));
        }
#pragma unroll
        for (int it = 0; it < 8; it++) {
            int c = (vcg + 2 * it) * 4;
            float4 v4 = *(const float4*)&Vsg[vrow * PSG + c];
            Vh[(c + 0) * PB + vrow] = __float2half_rn(v4.x);
            Vh[(c + 1) * PB + vrow] = __float2half_rn(v4.y);
            Vh[(c + 2) * PB + vrow] = __float2half_rn(v4.z);
            Vh[(c + 3) * PB + vrow] = __float2half_rn(v4.w);
        }
        __syncthreads();

        // ---- Stage next tile ----
        if (j0 + 64 < TSEQ) {
#pragma unroll
            for (int it = 0; it < 8; it++) {
                int r = sgr + 8 * it;
                cp16(ksg_s + (uint32_t)(r * PSG + sgc) * 4,
                     Kb + (size_t)(j0 + 64 + r) * D_MODEL + sgc);
                cp16(vsg_s + (uint32_t)(r * PSG + sgc) * 4,
                     Vb + (size_t)(j0 + 64 + r) * D_MODEL + sgc);
            }
            cp_commit();
        }

        // ---- S = (Qh + Ql) Kh^T ----
        float sacc[8][4];
#pragma unroll
        for (int j = 0; j < 8; j++)
#pragma unroll
            for (int i = 0; i < 4; i++) sacc[j][i] = 0.f;

#pragma unroll
        for (int u = 0; u < 4; u++) {
            const int w0 = u * 8 + t;
#pragma unroll
            for (int j = 0; j < 8; j++) {
                uint32_t kh0 = Kh32[(j * 8 + g) * PB32 + w0];
                uint32_t kh1 = Kh32[(j * 8 + g) * PB32 + w0 + 4];
                mma_f16(sacc[j], qfh[u], kh0, kh1);
                mma_f16(sacc[j], qfl[u], kh0, kh1);
            }
        }

        // ---- Online softmax ----
        float mx0 = -1e30f, mx1 = -1e30f;
#pragma unroll
        for (int j = 0; j < 8; j++) {
            mx0 = fmaxf(mx0, fmaxf(sacc[j][0], sacc[j][1]));
            mx1 = fmaxf(mx1, fmaxf(sacc[j][2], sacc[j][3]));
        }
        mx0 = fmaxf(mx0, __shfl_xor_sync(0xffffffffu, mx0, 1));
        mx0 = fmaxf(mx0, __shfl_xor_sync(0xffffffffu, mx0, 2));
        mx1 = fmaxf(mx1, __shfl_xor_sync(0xffffffffu, mx1, 1));
        mx1 = fmaxf(mx1, __shfl_xor_sync(0xffffffffu, mx1, 2));

        float mn0 = fmaxf(m0, mx0), mn1 = fmaxf(m1, mx1);
        float fac0 = __expf(m0 - mn0), fac1 = __expf(m1 - mn1);
        m0 = mn0; m1 = mn1;

        uint32_t ph01[8], ph23[8], pl01[8], pl23[8];
        float rs0 = 0.f, rs1 = 0.f;
#pragma unroll
        for (int j = 0; j < 8; j++) {
            float p0 = __expf(sacc[j][0] - mn0);
            float p1 = __expf(sacc[j][1] - mn0);
            float p2 = __expf(sacc[j][2] - mn1);
            float p3 = __expf(sacc[j][3] - mn1);
            rs0 += p0 + p1; rs1 += p2 + p3;
            __half h0, h1, h2, h3, q0, q1, q2, q3;
            hsplit(p0, h0, q0); hsplit(p1, h1, q1);
            hsplit(p2, h2, q2); hsplit(p3, h3, q3);
            ph01[j] = pack2h(h0, h1);
            ph23[j] = pack2h(h2, h3);
            pl01[j] = pack2h(q0, q1);
            pl23[j] = pack2h(q2, q3);
        }
        rs0 += __shfl_xor_sync(0xffffffffu, rs0, 1);
        rs0 += __shfl_xor_sync(0xffffffffu, rs0, 2);
        rs1 += __shfl_xor_sync(0xffffffffu, rs1, 1);
        rs1 += __shfl_xor_sync(0xffffffffu, rs1, 2);
        l0s = l0s * fac0 + rs0;
        l1s = l1s * fac1 + rs1;
#pragma unroll
        for (int j = 0; j < 8; j++) {
            oacc[j][0] *= fac0; oacc[j][1] *= fac0;
            oacc[j][2] *= fac1; oacc[j][3] *= fac1;
        }

        // ---- O += (Ph + Pl) Vh ----
#pragma unroll
        for (int u = 0; u < 4; u++) {
            const int w0 = u * 8 + t;
            uint32_t pfh[4] = { ph01[2 * u], ph23[2 * u], ph01[2 * u + 1], ph23[2 * u + 1] };
            uint32_t pfl[4] = { pl01[2 * u], pl23[2 * u], pl01[2 * u + 1], pl23[2 * u + 1] };
#pragma unroll
            for (int j = 0; j < 8; j++) {
                uint32_t vh0 = Vh32[(j * 8 + g) * PB32 + w0];
                uint32_t vh1 = Vh32[(j * 8 + g) * PB32 + w0 + 4];
                mma_f16(oacc[j], pfh, vh0, vh1);
                mma_f16(oacc[j], pfl, vh0, vh1);
            }
        }
    }

    // ---- Epilogue ----
    float inv0 = 1.f / l0s, inv1 = 1.f / l1s;
    float* Ob = O + base + (size_t)qt * 64 * D_MODEL;
#pragma unroll
    for (int j = 0; j < 8; j++) {
        int col = j * 8 + 2 * t;
        *(float2*)(Ob + (size_t)(row16 + g) * D_MODEL + col) =
            make_float2(oacc[j][0] * inv0, oacc[j][1] * inv0);
        *(float2*)(Ob + (size_t)(row16 + g + 8) * D_MODEL + col) =
            make_float2(oacc[j][2] * inv1, oacc[j][3] * inv1);
    }
}

// ---------------------------------------------------------------------------
// Launch. Input order:
// 0:q 1:k 2:v 3:W_q 4:b_q 5:W_k 6:b_k 7:W_v 8:b_v 9:W_o 10:b_o
// ---------------------------------------------------------------------------
extern "C" void kernel_launch(void* const* d_in, const int* in_sizes, int n_in,
                              void* d_out, int out_size)
{
    (void)in_sizes; (void)n_in; (void)out_size;
    const float* q   = (const float*)d_in[0];
    const float* k   = (const float*)d_in[1];
    const float* v   = (const float*)d_in[2];
    const float* W_q = (const float*)d_in[3];
    const float* b_q = (const float*)d_in[4];
    const float* W_k = (const float*)d_in[5];
    const float* b_k = (const float*)d_in[6];
    const float* W_v = (const float*)d_in[7];
    const float* b_v = (const float*)d_in[8];
    const float* W_o = (const float*)d_in[9];
    const float* b_o = (const float*)d_in[10];
    float* out = (float*)d_out;

    float *gQ, *gK, *gV, *gA;
    cudaGetSymbolAddress((void**)&gQ, g_Q);
    cudaGetSymbolAddress((void**)&gK, g_K);
    cudaGetSymbolAddress((void**)&gV, g_V);
    cudaGetSymbolAddress((void**)&gA, g_A);

    gemm_qkv_kernel<<<dim3(D_MODEL / BN, NTOK / BM, 3), 256>>>(
        q, k, v, W_q, W_k, W_v, b_q, b_k, b_v, gQ, gK, gV);

    cudaFuncSetAttribute(attention_f16_kernel,
                         cudaFuncAttributeMaxDynamicSharedMemorySize, ATT_SMEM);
    attention_f16_kernel<<<dim3(TSEQ / 64, HEADS, BATCH), 128, ATT_SMEM>>>(gQ, gK, gV, gA);

    gemm_o_kernel<<<dim3(D_MODEL / BN, NTOK / BM), 256>>>(gA, W_o, b_o, out);
}